// round 5
// baseline (speedup 1.0000x reference)
#include <cuda_runtime.h>
#include <math.h>

#define N_NODES_MAX 100000
#define N_EDGES_MAX 1600000
#define DIM 128
#define NCLS 40

// ---------------- scratch (static device allocations; no cudaMalloc) -------
__device__ int g_deg[N_NODES_MAX];
__device__ int g_offs[N_NODES_MAX + 1];
__device__ int g_cur[N_NODES_MAX];
__device__ int g_csr[N_EDGES_MAX];
__device__ __align__(16) float g_agg[(size_t)N_NODES_MAX * DIM];
__device__ __align__(16) float g_x1[(size_t)N_NODES_MAX * DIM];

// ---------------- CSR build -------------------------------------------------
__global__ void zero_deg_kernel(int n) {
    int i = blockIdx.x * blockDim.x + threadIdx.x;
    if (i < n) g_deg[i] = 0;
}

__global__ void hist_kernel(const int2* __restrict__ e, int m) {
    int i = blockIdx.x * blockDim.x + threadIdx.x;
    if (i < m) atomicAdd(&g_deg[e[i].y], 1);
}

// Single-block chunked exclusive scan: deg -> offs, cursor copy.
__global__ void scan_kernel(int n) {
    int t = threadIdx.x;
    int chunk = (n + 1023) >> 10;
    int b = t * chunk;
    int e = b + chunk;
    if (e > n) e = n;
    if (b > n) b = n;
    int sum = 0;
    for (int i = b; i < e; i++) sum += g_deg[i];

    int lane = t & 31, wid = t >> 5;
    int v = sum;
#pragma unroll
    for (int o = 1; o < 32; o <<= 1) {
        int u = __shfl_up_sync(0xffffffffu, v, o);
        if (lane >= o) v += u;
    }
    __shared__ int ws[32];
    if (lane == 31) ws[wid] = v;
    __syncthreads();
    if (wid == 0) {
        int w = ws[lane];
#pragma unroll
        for (int o = 1; o < 32; o <<= 1) {
            int u = __shfl_up_sync(0xffffffffu, w, o);
            if (lane >= o) w += u;
        }
        ws[lane] = w;
    }
    __syncthreads();
    int base = ((wid > 0) ? ws[wid - 1] : 0) + (v - sum);
    int run = base;
    for (int i = b; i < e; i++) {
        g_offs[i] = run;
        g_cur[i] = run;
        run += g_deg[i];
    }
    if (e == n) g_offs[n] = run;
}

__global__ void fill_kernel(const int2* __restrict__ e, int m) {
    int i = blockIdx.x * blockDim.x + threadIdx.x;
    if (i < m) {
        int2 ed = e[i];
        int p = atomicAdd(&g_cur[ed.y], 1);
        g_csr[p] = ed.x;
    }
}

// ---------------- aggregation: warp per node, 4-way pipelined gather --------
// out = x + sum_{s in N(i)} x[s]
__global__ __launch_bounds__(256) void agg_kernel(const float4* __restrict__ xin,
                                                  int n, int from_x1) {
    int gt = blockIdx.x * blockDim.x + threadIdx.x;
    int w = gt >> 5;
    int lane = gt & 31;
    if (w >= n) return;
    const float4* x4 = from_x1 ? (const float4*)g_x1 : xin;
    float4* o4 = (float4*)g_agg;

    float4 a0 = x4[(size_t)w * 32 + lane];  // self term
    float4 a1 = make_float4(0.f, 0.f, 0.f, 0.f);
    float4 a2 = make_float4(0.f, 0.f, 0.f, 0.f);
    float4 a3 = make_float4(0.f, 0.f, 0.f, 0.f);

    int j = g_offs[w], e = g_offs[w + 1];
    // 4-wide: 4 independent row loads in flight per warp (MLP_eff ~4)
    for (; j + 4 <= e; j += 4) {
        int s0 = g_csr[j + 0];
        int s1 = g_csr[j + 1];
        int s2 = g_csr[j + 2];
        int s3 = g_csr[j + 3];
        float4 v0 = __ldg(&x4[(size_t)s0 * 32 + lane]);
        float4 v1 = __ldg(&x4[(size_t)s1 * 32 + lane]);
        float4 v2 = __ldg(&x4[(size_t)s2 * 32 + lane]);
        float4 v3 = __ldg(&x4[(size_t)s3 * 32 + lane]);
        a0.x += v0.x; a0.y += v0.y; a0.z += v0.z; a0.w += v0.w;
        a1.x += v1.x; a1.y += v1.y; a1.z += v1.z; a1.w += v1.w;
        a2.x += v2.x; a2.y += v2.y; a2.z += v2.z; a2.w += v2.w;
        a3.x += v3.x; a3.y += v3.y; a3.z += v3.z; a3.w += v3.w;
    }
    for (; j < e; j++) {
        int s = g_csr[j];
        float4 v = __ldg(&x4[(size_t)s * 32 + lane]);
        a0.x += v.x; a0.y += v.y; a0.z += v.z; a0.w += v.w;
    }
    a0.x += a1.x + a2.x + a3.x;
    a0.y += a1.y + a2.y + a3.y;
    a0.z += a1.z + a2.z + a3.z;
    a0.w += a1.w + a2.w + a3.w;
    o4[(size_t)w * 32 + lane] = a0;
}

// ---------------- layer 1: x1 = relu(relu(agg@W1a+b1a)@W1b + b1b) -----------
#define G1_SMEM_FLOATS (64 * 129 + 128 * 128 + 128 + 128)
__global__ __launch_bounds__(256) void gemm1_kernel(
    const float* __restrict__ W1a, const float* __restrict__ b1a,
    const float* __restrict__ W1b, const float* __restrict__ b1b, int n) {
    extern __shared__ float sm[];
    float* As = sm;                    // 64 x 129 (padded)
    float* Wsh = sm + 64 * 129;        // 128 x 128
    float* bsA = Wsh + 128 * 128;      // 128
    float* bsB = bsA + 128;            // 128

    int tid = threadIdx.x;
    int tx = tid & 15, ty = tid >> 4;
    int row0 = blockIdx.x * 64;
    const float* A = g_agg;
    float* out = g_x1;

    for (int i = tid; i < 64 * 32; i += 256) {
        int r = i >> 5, c = i & 31;
        float4 v = (row0 + r < n) ? ((const float4*)A)[(size_t)(row0 + r) * 32 + c]
                                  : make_float4(0.f, 0.f, 0.f, 0.f);
        float* d = &As[r * 129 + c * 4];
        d[0] = v.x; d[1] = v.y; d[2] = v.z; d[3] = v.w;
    }
    for (int i = tid; i < 128 * 32; i += 256)
        ((float4*)Wsh)[i] = ((const float4*)W1a)[i];
    if (tid < 128) { bsA[tid] = b1a[tid]; bsB[tid] = b1b[tid]; }
    __syncthreads();

    float acc[4][8];
#pragma unroll
    for (int r = 0; r < 4; r++)
#pragma unroll
        for (int c = 0; c < 8; c++) acc[r][c] = 0.f;

    const float* a0 = &As[(ty * 4) * 129];
#pragma unroll 8
    for (int k = 0; k < 128; k++) {
        float av[4];
#pragma unroll
        for (int r = 0; r < 4; r++) av[r] = a0[r * 129 + k];
        float4 w0 = *(const float4*)&Wsh[k * 128 + tx * 8];
        float4 w1 = *(const float4*)&Wsh[k * 128 + tx * 8 + 4];
#pragma unroll
        for (int r = 0; r < 4; r++) {
            acc[r][0] = fmaf(av[r], w0.x, acc[r][0]);
            acc[r][1] = fmaf(av[r], w0.y, acc[r][1]);
            acc[r][2] = fmaf(av[r], w0.z, acc[r][2]);
            acc[r][3] = fmaf(av[r], w0.w, acc[r][3]);
            acc[r][4] = fmaf(av[r], w1.x, acc[r][4]);
            acc[r][5] = fmaf(av[r], w1.y, acc[r][5]);
            acc[r][6] = fmaf(av[r], w1.z, acc[r][6]);
            acc[r][7] = fmaf(av[r], w1.w, acc[r][7]);
        }
    }
    __syncthreads();

#pragma unroll
    for (int r = 0; r < 4; r++)
#pragma unroll
        for (int c = 0; c < 8; c++) {
            As[(ty * 4 + r) * 129 + tx * 8 + c] = fmaxf(acc[r][c] + bsA[tx * 8 + c], 0.f);
            acc[r][c] = 0.f;
        }
    for (int i = tid; i < 128 * 32; i += 256)
        ((float4*)Wsh)[i] = ((const float4*)W1b)[i];
    __syncthreads();

#pragma unroll 8
    for (int k = 0; k < 128; k++) {
        float av[4];
#pragma unroll
        for (int r = 0; r < 4; r++) av[r] = a0[r * 129 + k];
        float4 w0 = *(const float4*)&Wsh[k * 128 + tx * 8];
        float4 w1 = *(const float4*)&Wsh[k * 128 + tx * 8 + 4];
#pragma unroll
        for (int r = 0; r < 4; r++) {
            acc[r][0] = fmaf(av[r], w0.x, acc[r][0]);
            acc[r][1] = fmaf(av[r], w0.y, acc[r][1]);
            acc[r][2] = fmaf(av[r], w0.z, acc[r][2]);
            acc[r][3] = fmaf(av[r], w0.w, acc[r][3]);
            acc[r][4] = fmaf(av[r], w1.x, acc[r][4]);
            acc[r][5] = fmaf(av[r], w1.y, acc[r][5]);
            acc[r][6] = fmaf(av[r], w1.z, acc[r][6]);
            acc[r][7] = fmaf(av[r], w1.w, acc[r][7]);
        }
    }

#pragma unroll
    for (int r = 0; r < 4; r++) {
        int row = row0 + ty * 4 + r;
        if (row < n) {
            float4 o0, o1;
            o0.x = fmaxf(acc[r][0] + bsB[tx * 8 + 0], 0.f);
            o0.y = fmaxf(acc[r][1] + bsB[tx * 8 + 1], 0.f);
            o0.z = fmaxf(acc[r][2] + bsB[tx * 8 + 2], 0.f);
            o0.w = fmaxf(acc[r][3] + bsB[tx * 8 + 3], 0.f);
            o1.x = fmaxf(acc[r][4] + bsB[tx * 8 + 4], 0.f);
            o1.y = fmaxf(acc[r][5] + bsB[tx * 8 + 5], 0.f);
            o1.z = fmaxf(acc[r][6] + bsB[tx * 8 + 6], 0.f);
            o1.w = fmaxf(acc[r][7] + bsB[tx * 8 + 7], 0.f);
            float4* dst = (float4*)&out[(size_t)row * 128 + tx * 8];
            dst[0] = o0;
            dst[1] = o1;
        }
    }
}

// ---------------- layer 2 + softmax -----------------------------------------
// 256 rows per block, 256 threads, thread-per-row.
#define G2_ROWS 256
#define G2_SMEM_FLOATS (G2_ROWS * 129 + 128 * 40 + 40 * 40 + 40 + 40)
__global__ __launch_bounds__(256) void gemm2_kernel(
    const float* __restrict__ W2a, const float* __restrict__ b2a,
    const float* __restrict__ W2b, const float* __restrict__ b2b,
    float* __restrict__ out, int n) {
    extern __shared__ float sm[];
    float* As = sm;                       // 256 x 129 (padded)
    float* Wa = sm + G2_ROWS * 129;       // 128 x 40
    float* Wb = Wa + 128 * 40;            // 40 x 40
    float* ba = Wb + 40 * 40;             // 40
    float* bb = ba + 40;                  // 40

    int tid = threadIdx.x;
    int row0 = blockIdx.x * G2_ROWS;
    const float* A = g_agg;

    for (int i = tid; i < G2_ROWS * 32; i += 256) {
        int r = i >> 5, c = i & 31;
        float4 v = (row0 + r < n) ? ((const float4*)A)[(size_t)(row0 + r) * 32 + c]
                                  : make_float4(0.f, 0.f, 0.f, 0.f);
        float* d = &As[r * 129 + c * 4];
        d[0] = v.x; d[1] = v.y; d[2] = v.z; d[3] = v.w;
    }
    for (int i = tid; i < 128 * 10; i += 256)
        ((float4*)Wa)[i] = ((const float4*)W2a)[i];
    for (int i = tid; i < 1600; i += 256) Wb[i] = W2b[i];
    if (tid < 40) { ba[tid] = b2a[tid]; bb[tid] = b2b[tid]; }
    __syncthreads();

    float h[40];
#pragma unroll
    for (int c = 0; c < 40; c++) h[c] = ba[c];
    const float* arow = &As[tid * 129];
#pragma unroll 4
    for (int k = 0; k < 128; k++) {
        float a = arow[k];
        const float4* w = (const float4*)&Wa[k * 40];
#pragma unroll
        for (int q = 0; q < 10; q++) {
            float4 wv = w[q];
            h[q * 4 + 0] = fmaf(a, wv.x, h[q * 4 + 0]);
            h[q * 4 + 1] = fmaf(a, wv.y, h[q * 4 + 1]);
            h[q * 4 + 2] = fmaf(a, wv.z, h[q * 4 + 2]);
            h[q * 4 + 3] = fmaf(a, wv.w, h[q * 4 + 3]);
        }
    }
    float o[40];
#pragma unroll
    for (int c = 0; c < 40; c++) { o[c] = bb[c]; h[c] = fmaxf(h[c], 0.f); }
#pragma unroll 4
    for (int k = 0; k < 40; k++) {
        float a = h[k];
        const float4* w = (const float4*)&Wb[k * 40];
#pragma unroll
        for (int q = 0; q < 10; q++) {
            float4 wv = w[q];
            o[q * 4 + 0] = fmaf(a, wv.x, o[q * 4 + 0]);
            o[q * 4 + 1] = fmaf(a, wv.y, o[q * 4 + 1]);
            o[q * 4 + 2] = fmaf(a, wv.z, o[q * 4 + 2]);
            o[q * 4 + 3] = fmaf(a, wv.w, o[q * 4 + 3]);
        }
    }
    float mx = o[0];
#pragma unroll
    for (int c = 1; c < 40; c++) mx = fmaxf(mx, o[c]);
    float s = 0.f;
#pragma unroll
    for (int c = 0; c < 40; c++) { float e = __expf(o[c] - mx); o[c] = e; s += e; }
    float inv = 1.0f / s;
#pragma unroll
    for (int c = 0; c < 40; c++) o[c] *= inv;

#pragma unroll
    for (int c = 0; c < 40; c++) As[tid * 129 + c] = o[c];
    __syncthreads();
    for (int i = tid; i < G2_ROWS * 40; i += 256) {
        int r = i / 40, c = i - r * 40;
        int row = row0 + r;
        if (row < n) out[(size_t)row * 40 + c] = As[r * 129 + c];
    }
}

// ---------------- launcher --------------------------------------------------
extern "C" void kernel_launch(void* const* d_in, const int* in_sizes, int n_in,
                              void* d_out, int out_size) {
    int i_nodes = 0, i_edges = -1;
    for (int i = 1; i < n_in; i++)
        if (in_sizes[i] > in_sizes[i_nodes]) i_nodes = i;
    for (int i = 0; i < n_in; i++) {
        if (i == i_nodes) continue;
        if (i_edges < 0 || in_sizes[i] > in_sizes[i_edges]) i_edges = i;
    }

    const float* x0  = (const float*)d_in[i_nodes];
    const int2*  ei  = (const int2*)d_in[i_edges];
    int n = in_sizes[i_nodes] / DIM;
    int m = in_sizes[i_edges] / 2;

    const float *W1a = 0, *W1b = 0, *b1a = 0, *b1b = 0;
    const float *W2a = 0, *W2b = 0, *b2a = 0, *b2b = 0;
    for (int i = 0; i < n_in; i++) {
        if (i == i_nodes || i == i_edges) continue;
        int s = in_sizes[i];
        const float* p = (const float*)d_in[i];
        if (s == DIM * DIM)        { if (!W1a) W1a = p; else W1b = p; }
        else if (s == DIM)         { if (!b1a) b1a = p; else b1b = p; }
        else if (s == DIM * NCLS)  W2a = p;
        else if (s == NCLS * NCLS) W2b = p;
        else if (s == NCLS)        { if (!b2a) b2a = p; else b2b = p; }
    }
    float* out = (float*)d_out;

    const int g1_smem = G1_SMEM_FLOATS * (int)sizeof(float);
    const int g2_smem = G2_SMEM_FLOATS * (int)sizeof(float);
    cudaFuncSetAttribute(gemm1_kernel, cudaFuncAttributeMaxDynamicSharedMemorySize, g1_smem);
    cudaFuncSetAttribute(gemm2_kernel, cudaFuncAttributeMaxDynamicSharedMemorySize, g2_smem);

    // CSR build (shared by both layers)
    zero_deg_kernel<<<(n + 255) / 256, 256>>>(n);
    hist_kernel<<<(m + 255) / 256, 256>>>(ei, m);
    scan_kernel<<<1, 1024>>>(n);
    fill_kernel<<<(m + 255) / 256, 256>>>(ei, m);

    // layer 1
    agg_kernel<<<((size_t)n * 32 + 255) / 256, 256>>>((const float4*)x0, n, 0);
    gemm1_kernel<<<(n + 63) / 64, 256, g1_smem>>>(W1a, b1a, W1b, b1b, n);

    // layer 2
    agg_kernel<<<((size_t)n * 32 + 255) / 256, 256>>>((const float4*)x0, n, 1);
    gemm2_kernel<<<(n + G2_ROWS - 1) / G2_ROWS, 256, g2_smem>>>(W2a, b2a, W2b, b2b, out, n);
}

// round 6
// speedup vs baseline: 1.0794x; 1.0794x over previous
#include <cuda_runtime.h>
#include <math.h>

#define N_NODES_MAX 100000
#define N_EDGES_MAX 1600000
#define DIM 128
#define NCLS 40

// ---------------- scratch (static device allocations; no cudaMalloc) -------
__device__ int g_deg[N_NODES_MAX];
__device__ int g_offs[N_NODES_MAX + 1];
__device__ int g_cur[N_NODES_MAX];
__device__ int g_csr[N_EDGES_MAX];
__device__ __align__(16) float g_agg[(size_t)N_NODES_MAX * DIM];   // also reused for aggy
__device__ __align__(16) float g_x1[(size_t)N_NODES_MAX * DIM];
__device__ __align__(16) float g_y1[(size_t)N_NODES_MAX * NCLS];

// ---------------- CSR build -------------------------------------------------
__global__ void zero_deg_kernel(int n) {
    int i = blockIdx.x * blockDim.x + threadIdx.x;
    if (i < n) g_deg[i] = 0;
}

__global__ void hist_kernel(const int2* __restrict__ e, int m) {
    int i = blockIdx.x * blockDim.x + threadIdx.x;
    if (i < m) atomicAdd(&g_deg[e[i].y], 1);
}

__global__ void scan_kernel(int n) {
    int t = threadIdx.x;
    int chunk = (n + 1023) >> 10;
    int b = t * chunk;
    int e = b + chunk;
    if (e > n) e = n;
    if (b > n) b = n;
    int sum = 0;
    for (int i = b; i < e; i++) sum += g_deg[i];

    int lane = t & 31, wid = t >> 5;
    int v = sum;
#pragma unroll
    for (int o = 1; o < 32; o <<= 1) {
        int u = __shfl_up_sync(0xffffffffu, v, o);
        if (lane >= o) v += u;
    }
    __shared__ int ws[32];
    if (lane == 31) ws[wid] = v;
    __syncthreads();
    if (wid == 0) {
        int w = ws[lane];
#pragma unroll
        for (int o = 1; o < 32; o <<= 1) {
            int u = __shfl_up_sync(0xffffffffu, w, o);
            if (lane >= o) w += u;
        }
        ws[lane] = w;
    }
    __syncthreads();
    int base = ((wid > 0) ? ws[wid - 1] : 0) + (v - sum);
    int run = base;
    for (int i = b; i < e; i++) {
        g_offs[i] = run;
        g_cur[i] = run;
        run += g_deg[i];
    }
    if (e == n) g_offs[n] = run;
}

__global__ void fill_kernel(const int2* __restrict__ e, int m) {
    int i = blockIdx.x * blockDim.x + threadIdx.x;
    if (i < m) {
        int2 ed = e[i];
        int p = atomicAdd(&g_cur[ed.y], 1);
        g_csr[p] = ed.x;
    }
}

// ---------------- agg1: warp per node, 128-dim gather (round-4 proven) ------
__global__ __launch_bounds__(256) void agg_kernel(const float4* __restrict__ x4, int n) {
    int gt = blockIdx.x * blockDim.x + threadIdx.x;
    int w = gt >> 5;
    int lane = gt & 31;
    if (w >= n) return;
    float4* o4 = (float4*)g_agg;
    float4 acc = x4[(size_t)w * 32 + lane];
    int s0 = g_offs[w], s1 = g_offs[w + 1];
    for (int j = s0; j < s1; j++) {
        int s = g_csr[j];
        float4 v = __ldg(&x4[(size_t)s * 32 + lane]);
        acc.x += v.x; acc.y += v.y; acc.z += v.z; acc.w += v.w;
    }
    o4[(size_t)w * 32 + lane] = acc;
}

// ---------------- layer 1: x1 = relu(relu(agg@W1a+b1a)@W1b + b1b) -----------
#define G1_SMEM_FLOATS (64 * 129 + 128 * 128 + 128 + 128)
__global__ __launch_bounds__(256) void gemm1_kernel(
    const float* __restrict__ W1a, const float* __restrict__ b1a,
    const float* __restrict__ W1b, const float* __restrict__ b1b, int n) {
    extern __shared__ float sm[];
    float* As = sm;                    // 64 x 129 (padded)
    float* Wsh = sm + 64 * 129;        // 128 x 128
    float* bsA = Wsh + 128 * 128;      // 128
    float* bsB = bsA + 128;            // 128

    int tid = threadIdx.x;
    int tx = tid & 15, ty = tid >> 4;
    int row0 = blockIdx.x * 64;
    const float* A = g_agg;
    float* out = g_x1;

    for (int i = tid; i < 64 * 32; i += 256) {
        int r = i >> 5, c = i & 31;
        float4 v = (row0 + r < n) ? ((const float4*)A)[(size_t)(row0 + r) * 32 + c]
                                  : make_float4(0.f, 0.f, 0.f, 0.f);
        float* d = &As[r * 129 + c * 4];
        d[0] = v.x; d[1] = v.y; d[2] = v.z; d[3] = v.w;
    }
    for (int i = tid; i < 128 * 32; i += 256)
        ((float4*)Wsh)[i] = ((const float4*)W1a)[i];
    if (tid < 128) { bsA[tid] = b1a[tid]; bsB[tid] = b1b[tid]; }
    __syncthreads();

    float acc[4][8];
#pragma unroll
    for (int r = 0; r < 4; r++)
#pragma unroll
        for (int c = 0; c < 8; c++) acc[r][c] = 0.f;

    const float* a0 = &As[(ty * 4) * 129];
#pragma unroll 8
    for (int k = 0; k < 128; k++) {
        float av[4];
#pragma unroll
        for (int r = 0; r < 4; r++) av[r] = a0[r * 129 + k];
        float4 w0 = *(const float4*)&Wsh[k * 128 + tx * 8];
        float4 w1 = *(const float4*)&Wsh[k * 128 + tx * 8 + 4];
#pragma unroll
        for (int r = 0; r < 4; r++) {
            acc[r][0] = fmaf(av[r], w0.x, acc[r][0]);
            acc[r][1] = fmaf(av[r], w0.y, acc[r][1]);
            acc[r][2] = fmaf(av[r], w0.z, acc[r][2]);
            acc[r][3] = fmaf(av[r], w0.w, acc[r][3]);
            acc[r][4] = fmaf(av[r], w1.x, acc[r][4]);
            acc[r][5] = fmaf(av[r], w1.y, acc[r][5]);
            acc[r][6] = fmaf(av[r], w1.z, acc[r][6]);
            acc[r][7] = fmaf(av[r], w1.w, acc[r][7]);
        }
    }
    __syncthreads();

#pragma unroll
    for (int r = 0; r < 4; r++)
#pragma unroll
        for (int c = 0; c < 8; c++) {
            As[(ty * 4 + r) * 129 + tx * 8 + c] = fmaxf(acc[r][c] + bsA[tx * 8 + c], 0.f);
            acc[r][c] = 0.f;
        }
    for (int i = tid; i < 128 * 32; i += 256)
        ((float4*)Wsh)[i] = ((const float4*)W1b)[i];
    __syncthreads();

#pragma unroll 8
    for (int k = 0; k < 128; k++) {
        float av[4];
#pragma unroll
        for (int r = 0; r < 4; r++) av[r] = a0[r * 129 + k];
        float4 w0 = *(const float4*)&Wsh[k * 128 + tx * 8];
        float4 w1 = *(const float4*)&Wsh[k * 128 + tx * 8 + 4];
#pragma unroll
        for (int r = 0; r < 4; r++) {
            acc[r][0] = fmaf(av[r], w0.x, acc[r][0]);
            acc[r][1] = fmaf(av[r], w0.y, acc[r][1]);
            acc[r][2] = fmaf(av[r], w0.z, acc[r][2]);
            acc[r][3] = fmaf(av[r], w0.w, acc[r][3]);
            acc[r][4] = fmaf(av[r], w1.x, acc[r][4]);
            acc[r][5] = fmaf(av[r], w1.y, acc[r][5]);
            acc[r][6] = fmaf(av[r], w1.z, acc[r][6]);
            acc[r][7] = fmaf(av[r], w1.w, acc[r][7]);
        }
    }

#pragma unroll
    for (int r = 0; r < 4; r++) {
        int row = row0 + ty * 4 + r;
        if (row < n) {
            float4 o0, o1;
            o0.x = fmaxf(acc[r][0] + bsB[tx * 8 + 0], 0.f);
            o0.y = fmaxf(acc[r][1] + bsB[tx * 8 + 1], 0.f);
            o0.z = fmaxf(acc[r][2] + bsB[tx * 8 + 2], 0.f);
            o0.w = fmaxf(acc[r][3] + bsB[tx * 8 + 3], 0.f);
            o1.x = fmaxf(acc[r][4] + bsB[tx * 8 + 4], 0.f);
            o1.y = fmaxf(acc[r][5] + bsB[tx * 8 + 5], 0.f);
            o1.z = fmaxf(acc[r][6] + bsB[tx * 8 + 6], 0.f);
            o1.w = fmaxf(acc[r][7] + bsB[tx * 8 + 7], 0.f);
            float4* dst = (float4*)&out[(size_t)row * 128 + tx * 8];
            dst[0] = o0;
            dst[1] = o1;
        }
    }
}

// ---------------- y1 = x1 @ W2a  (projection BEFORE aggregation) ------------
// segment_sum is linear: agg(x1) @ W2a == agg(x1 @ W2a). 3.2x less gather traffic.
#define Y1_SMEM_FLOATS (128 * 129 + 128 * 40)
__global__ __launch_bounds__(128) void y1_kernel(const float* __restrict__ W2a, int n) {
    extern __shared__ float sm[];
    float* As = sm;                  // 128 x 129 (padded)
    float* Wa = sm + 128 * 129;      // 128 x 40

    int tid = threadIdx.x;
    int row0 = blockIdx.x * 128;
    const float* A = g_x1;

    for (int i = tid; i < 128 * 32; i += 128) {
        int r = i >> 5, c = i & 31;
        float4 v = (row0 + r < n) ? ((const float4*)A)[(size_t)(row0 + r) * 32 + c]
                                  : make_float4(0.f, 0.f, 0.f, 0.f);
        float* d = &As[r * 129 + c * 4];
        d[0] = v.x; d[1] = v.y; d[2] = v.z; d[3] = v.w;
    }
    for (int i = tid; i < 128 * 10; i += 128)
        ((float4*)Wa)[i] = ((const float4*)W2a)[i];
    __syncthreads();

    float h[40];
#pragma unroll
    for (int c = 0; c < 40; c++) h[c] = 0.f;
    const float* arow = &As[tid * 129];
#pragma unroll 4
    for (int k = 0; k < 128; k++) {
        float a = arow[k];
        const float4* w = (const float4*)&Wa[k * 40];
#pragma unroll
        for (int q = 0; q < 10; q++) {
            float4 wv = w[q];
            h[q * 4 + 0] = fmaf(a, wv.x, h[q * 4 + 0]);
            h[q * 4 + 1] = fmaf(a, wv.y, h[q * 4 + 1]);
            h[q * 4 + 2] = fmaf(a, wv.z, h[q * 4 + 2]);
            h[q * 4 + 3] = fmaf(a, wv.w, h[q * 4 + 3]);
        }
    }
    // restage own row, then coalesced store
#pragma unroll
    for (int c = 0; c < 40; c++) As[tid * 129 + c] = h[c];
    __syncthreads();
    for (int i = tid; i < 128 * 40; i += 128) {
        int r = i / 40, c = i - r * 40;
        int row = row0 + r;
        if (row < n) g_y1[(size_t)row * 40 + c] = As[r * 129 + c];
    }
}

// ---------------- agg2: warp per node, 40-dim gather (lanes 0-19, float2) ---
__global__ __launch_bounds__(256) void agg2_kernel(int n) {
    int gt = blockIdx.x * blockDim.x + threadIdx.x;
    int w = gt >> 5;
    int lane = gt & 31;
    if (w >= n || lane >= 20) return;
    const float2* y2 = (const float2*)g_y1;
    float2* o2 = (float2*)g_agg;  // reuse g_agg as aggy (100k x 40)
    float2 acc = y2[(size_t)w * 20 + lane];  // self term
    int s0 = g_offs[w], s1 = g_offs[w + 1];
    for (int j = s0; j < s1; j++) {
        int s = g_csr[j];
        float2 v = __ldg(&y2[(size_t)s * 20 + lane]);
        acc.x += v.x; acc.y += v.y;
    }
    o2[(size_t)w * 20 + lane] = acc;
}

// ---------------- final: out = softmax(relu(aggy + b2a) @ W2b + b2b) --------
#define G2B_ROWS 256
#define G2B_SMEM_FLOATS (G2B_ROWS * 41 + 40 * 40 + 40 + 40)
__global__ __launch_bounds__(256) void gemm2b_kernel(
    const float* __restrict__ b2a, const float* __restrict__ W2b,
    const float* __restrict__ b2b, float* __restrict__ out, int n) {
    extern __shared__ float sm[];
    float* As = sm;                       // 256 x 41 (padded)
    float* Wb = sm + G2B_ROWS * 41;       // 40 x 40
    float* ba = Wb + 40 * 40;             // 40
    float* bb = ba + 40;                  // 40

    int tid = threadIdx.x;
    int row0 = blockIdx.x * G2B_ROWS;
    const float* A = g_agg;  // aggy

    for (int i = tid; i < G2B_ROWS * 40; i += 256) {
        int r = i / 40, c = i - r * 40;
        int row = row0 + r;
        As[r * 41 + c] = (row < n) ? A[(size_t)row * 40 + c] : 0.f;
    }
    for (int i = tid; i < 1600; i += 256) Wb[i] = W2b[i];
    if (tid < 40) { ba[tid] = b2a[tid]; bb[tid] = b2b[tid]; }
    __syncthreads();

    float h[40];
    const float* arow = &As[tid * 41];
#pragma unroll
    for (int c = 0; c < 40; c++) h[c] = fmaxf(arow[c] + ba[c], 0.f);

    float o[40];
#pragma unroll
    for (int c = 0; c < 40; c++) o[c] = bb[c];
#pragma unroll 4
    for (int k = 0; k < 40; k++) {
        float a = h[k];
        const float4* w = (const float4*)&Wb[k * 40];
#pragma unroll
        for (int q = 0; q < 10; q++) {
            float4 wv = w[q];
            o[q * 4 + 0] = fmaf(a, wv.x, o[q * 4 + 0]);
            o[q * 4 + 1] = fmaf(a, wv.y, o[q * 4 + 1]);
            o[q * 4 + 2] = fmaf(a, wv.z, o[q * 4 + 2]);
            o[q * 4 + 3] = fmaf(a, wv.w, o[q * 4 + 3]);
        }
    }
    float mx = o[0];
#pragma unroll
    for (int c = 1; c < 40; c++) mx = fmaxf(mx, o[c]);
    float s = 0.f;
#pragma unroll
    for (int c = 0; c < 40; c++) { float e = __expf(o[c] - mx); o[c] = e; s += e; }
    float inv = 1.0f / s;
#pragma unroll
    for (int c = 0; c < 40; c++) As[tid * 41 + c] = o[c] * inv;
    __syncthreads();
    for (int i = tid; i < G2B_ROWS * 40; i += 256) {
        int r = i / 40, c = i - r * 40;
        int row = row0 + r;
        if (row < n) out[(size_t)row * 40 + c] = As[r * 41 + c];
    }
}

// ---------------- launcher --------------------------------------------------
extern "C" void kernel_launch(void* const* d_in, const int* in_sizes, int n_in,
                              void* d_out, int out_size) {
    int i_nodes = 0, i_edges = -1;
    for (int i = 1; i < n_in; i++)
        if (in_sizes[i] > in_sizes[i_nodes]) i_nodes = i;
    for (int i = 0; i < n_in; i++) {
        if (i == i_nodes) continue;
        if (i_edges < 0 || in_sizes[i] > in_sizes[i_edges]) i_edges = i;
    }

    const float* x0  = (const float*)d_in[i_nodes];
    const int2*  ei  = (const int2*)d_in[i_edges];
    int n = in_sizes[i_nodes] / DIM;
    int m = in_sizes[i_edges] / 2;

    const float *W1a = 0, *W1b = 0, *b1a = 0, *b1b = 0;
    const float *W2a = 0, *W2b = 0, *b2a = 0, *b2b = 0;
    for (int i = 0; i < n_in; i++) {
        if (i == i_nodes || i == i_edges) continue;
        int s = in_sizes[i];
        const float* p = (const float*)d_in[i];
        if (s == DIM * DIM)        { if (!W1a) W1a = p; else W1b = p; }
        else if (s == DIM)         { if (!b1a) b1a = p; else b1b = p; }
        else if (s == DIM * NCLS)  W2a = p;
        else if (s == NCLS * NCLS) W2b = p;
        else if (s == NCLS)        { if (!b2a) b2a = p; else b2b = p; }
    }
    float* out = (float*)d_out;

    const int g1_smem  = G1_SMEM_FLOATS * (int)sizeof(float);
    const int y1_smem  = Y1_SMEM_FLOATS * (int)sizeof(float);
    const int g2b_smem = G2B_SMEM_FLOATS * (int)sizeof(float);
    cudaFuncSetAttribute(gemm1_kernel, cudaFuncAttributeMaxDynamicSharedMemorySize, g1_smem);
    cudaFuncSetAttribute(y1_kernel, cudaFuncAttributeMaxDynamicSharedMemorySize, y1_smem);
    cudaFuncSetAttribute(gemm2b_kernel, cudaFuncAttributeMaxDynamicSharedMemorySize, g2b_smem);

    // CSR build (shared by both layers)
    zero_deg_kernel<<<(n + 255) / 256, 256>>>(n);
    hist_kernel<<<(m + 255) / 256, 256>>>(ei, m);
    scan_kernel<<<1, 1024>>>(n);
    fill_kernel<<<(m + 255) / 256, 256>>>(ei, m);

    // layer 1
    agg_kernel<<<((size_t)n * 32 + 255) / 256, 256>>>((const float4*)x0, n);
    gemm1_kernel<<<(n + 63) / 64, 256, g1_smem>>>(W1a, b1a, W1b, b1b, n);

    // layer 2 (project -> aggregate -> tiny GEMM + softmax)
    y1_kernel<<<(n + 127) / 128, 128, y1_smem>>>(W2a, n);
    agg2_kernel<<<((size_t)n * 32 + 255) / 256, 256>>>(n);
    gemm2b_kernel<<<(n + G2B_ROWS - 1) / G2B_ROWS, 256, g2b_smem>>>(b2a, W2b, b2b, out, n);
}

// round 7
// speedup vs baseline: 1.0810x; 1.0015x over previous
#include <cuda_runtime.h>
#include <math.h>

#define N_NODES_MAX 100000
#define N_EDGES_MAX 1600000
#define DIM 128
#define NCLS 40

// ---------------- f32x2 packed-FMA helpers (sm_103a FFMA2) ------------------
__device__ __forceinline__ unsigned long long pack2(float lo, float hi) {
    unsigned long long v;
    asm("mov.b64 %0, {%1, %2};" : "=l"(v) : "f"(lo), "f"(hi));
    return v;
}
__device__ __forceinline__ float2 unpack2(unsigned long long v) {
    float2 r;
    asm("mov.b64 {%0, %1}, %2;" : "=f"(r.x), "=f"(r.y) : "l"(v));
    return r;
}
__device__ __forceinline__ void fma2(unsigned long long& d, unsigned long long a,
                                     unsigned long long b) {
    asm("fma.rn.f32x2 %0, %1, %2, %0;" : "+l"(d) : "l"(a), "l"(b));
}

// ---------------- scratch (static device allocations; no cudaMalloc) -------
__device__ int g_deg[N_NODES_MAX];
__device__ int g_offs[N_NODES_MAX + 1];
__device__ int g_cur[N_NODES_MAX];
__device__ int g_csr[N_EDGES_MAX];
__device__ __align__(16) float g_agg[(size_t)N_NODES_MAX * DIM];   // also reused for aggy
__device__ __align__(16) float g_x1[(size_t)N_NODES_MAX * DIM];
__device__ __align__(16) float g_y1[(size_t)N_NODES_MAX * NCLS];

// ---------------- CSR build -------------------------------------------------
__global__ void zero_deg_kernel(int n) {
    int i = blockIdx.x * blockDim.x + threadIdx.x;
    if (i < n) g_deg[i] = 0;
}

__global__ void hist_kernel(const int2* __restrict__ e, int m) {
    int i = blockIdx.x * blockDim.x + threadIdx.x;
    if (i < m) atomicAdd(&g_deg[e[i].y], 1);
}

__global__ void scan_kernel(int n) {
    int t = threadIdx.x;
    int chunk = (n + 1023) >> 10;
    int b = t * chunk;
    int e = b + chunk;
    if (e > n) e = n;
    if (b > n) b = n;
    int sum = 0;
    for (int i = b; i < e; i++) sum += g_deg[i];

    int lane = t & 31, wid = t >> 5;
    int v = sum;
#pragma unroll
    for (int o = 1; o < 32; o <<= 1) {
        int u = __shfl_up_sync(0xffffffffu, v, o);
        if (lane >= o) v += u;
    }
    __shared__ int ws[32];
    if (lane == 31) ws[wid] = v;
    __syncthreads();
    if (wid == 0) {
        int w = ws[lane];
#pragma unroll
        for (int o = 1; o < 32; o <<= 1) {
            int u = __shfl_up_sync(0xffffffffu, w, o);
            if (lane >= o) w += u;
        }
        ws[lane] = w;
    }
    __syncthreads();
    int base = ((wid > 0) ? ws[wid - 1] : 0) + (v - sum);
    int run = base;
    for (int i = b; i < e; i++) {
        g_offs[i] = run;
        g_cur[i] = run;
        run += g_deg[i];
    }
    if (e == n) g_offs[n] = run;
}

__global__ void fill_kernel(const int2* __restrict__ e, int m) {
    int i = blockIdx.x * blockDim.x + threadIdx.x;
    if (i < m) {
        int2 ed = e[i];
        int p = atomicAdd(&g_cur[ed.y], 1);
        g_csr[p] = ed.x;
    }
}

// ---------------- agg1: warp per node, 128-dim gather -----------------------
__global__ __launch_bounds__(256) void agg_kernel(const float4* __restrict__ x4, int n) {
    int gt = blockIdx.x * blockDim.x + threadIdx.x;
    int w = gt >> 5;
    int lane = gt & 31;
    if (w >= n) return;
    float4* o4 = (float4*)g_agg;
    float4 acc = x4[(size_t)w * 32 + lane];
    int s0 = g_offs[w], s1 = g_offs[w + 1];
    for (int j = s0; j < s1; j++) {
        int s = g_csr[j];
        float4 v = __ldg(&x4[(size_t)s * 32 + lane]);
        acc.x += v.x; acc.y += v.y; acc.z += v.z; acc.w += v.w;
    }
    o4[(size_t)w * 32 + lane] = acc;
}

// ---------------- layer 1: x1 = relu(relu(agg@W1a+b1a)@W1b + b1b) -----------
// Inner product via packed fma.rn.f32x2 (2 fp32 FMA per issue slot).
#define G1_SMEM_FLOATS (64 * 129 + 128 * 128 + 128 + 128)
__global__ __launch_bounds__(256) void gemm1_kernel(
    const float* __restrict__ W1a, const float* __restrict__ b1a,
    const float* __restrict__ W1b, const float* __restrict__ b1b, int n) {
    extern __shared__ float sm[];
    float* As = sm;                    // 64 x 129 (padded)
    float* Wsh = sm + 64 * 129;        // 128 x 128
    float* bsA = Wsh + 128 * 128;      // 128
    float* bsB = bsA + 128;            // 128

    int tid = threadIdx.x;
    int tx = tid & 15, ty = tid >> 4;  // thread owns 4 rows x 8 cols (4 f32x2 pairs)
    int row0 = blockIdx.x * 64;
    const float* A = g_agg;
    float* out = g_x1;

    for (int i = tid; i < 64 * 32; i += 256) {
        int r = i >> 5, c = i & 31;
        float4 v = (row0 + r < n) ? ((const float4*)A)[(size_t)(row0 + r) * 32 + c]
                                  : make_float4(0.f, 0.f, 0.f, 0.f);
        float* d = &As[r * 129 + c * 4];
        d[0] = v.x; d[1] = v.y; d[2] = v.z; d[3] = v.w;
    }
    for (int i = tid; i < 128 * 32; i += 256)
        ((float4*)Wsh)[i] = ((const float4*)W1a)[i];
    if (tid < 128) { bsA[tid] = b1a[tid]; bsB[tid] = b1b[tid]; }
    __syncthreads();

    unsigned long long acc2[4][4];  // [row][col-pair]
#pragma unroll
    for (int r = 0; r < 4; r++)
#pragma unroll
        for (int c = 0; c < 4; c++) acc2[r][c] = 0ull;

    const float* a0 = &As[(ty * 4) * 129];
#pragma unroll 8
    for (int k = 0; k < 128; k++) {
        unsigned long long av2[4];
#pragma unroll
        for (int r = 0; r < 4; r++) {
            float a = a0[r * 129 + k];
            av2[r] = pack2(a, a);
        }
        const ulonglong2* wp = (const ulonglong2*)&Wsh[k * 128 + tx * 8];
        ulonglong2 wA = wp[0];  // pairs (c0,c1), (c2,c3)
        ulonglong2 wB = wp[1];  // pairs (c4,c5), (c6,c7)
#pragma unroll
        for (int r = 0; r < 4; r++) {
            fma2(acc2[r][0], av2[r], wA.x);
            fma2(acc2[r][1], av2[r], wA.y);
            fma2(acc2[r][2], av2[r], wB.x);
            fma2(acc2[r][3], av2[r], wB.y);
        }
    }
    __syncthreads();

    // H = relu(acc + b1a) back into As; swap W1b into Wsh
#pragma unroll
    for (int r = 0; r < 4; r++)
#pragma unroll
        for (int c = 0; c < 4; c++) {
            float2 p = unpack2(acc2[r][c]);
            As[(ty * 4 + r) * 129 + tx * 8 + 2 * c + 0] = fmaxf(p.x + bsA[tx * 8 + 2 * c + 0], 0.f);
            As[(ty * 4 + r) * 129 + tx * 8 + 2 * c + 1] = fmaxf(p.y + bsA[tx * 8 + 2 * c + 1], 0.f);
            acc2[r][c] = 0ull;
        }
    for (int i = tid; i < 128 * 32; i += 256)
        ((float4*)Wsh)[i] = ((const float4*)W1b)[i];
    __syncthreads();

#pragma unroll 8
    for (int k = 0; k < 128; k++) {
        unsigned long long av2[4];
#pragma unroll
        for (int r = 0; r < 4; r++) {
            float a = a0[r * 129 + k];
            av2[r] = pack2(a, a);
        }
        const ulonglong2* wp = (const ulonglong2*)&Wsh[k * 128 + tx * 8];
        ulonglong2 wA = wp[0];
        ulonglong2 wB = wp[1];
#pragma unroll
        for (int r = 0; r < 4; r++) {
            fma2(acc2[r][0], av2[r], wA.x);
            fma2(acc2[r][1], av2[r], wA.y);
            fma2(acc2[r][2], av2[r], wB.x);
            fma2(acc2[r][3], av2[r], wB.y);
        }
    }

    // x1 = relu(acc + b1b), coalesced float4 stores
#pragma unroll
    for (int r = 0; r < 4; r++) {
        int row = row0 + ty * 4 + r;
        if (row < n) {
            float2 p0 = unpack2(acc2[r][0]);
            float2 p1 = unpack2(acc2[r][1]);
            float2 p2 = unpack2(acc2[r][2]);
            float2 p3 = unpack2(acc2[r][3]);
            float4 o0, o1;
            o0.x = fmaxf(p0.x + bsB[tx * 8 + 0], 0.f);
            o0.y = fmaxf(p0.y + bsB[tx * 8 + 1], 0.f);
            o0.z = fmaxf(p1.x + bsB[tx * 8 + 2], 0.f);
            o0.w = fmaxf(p1.y + bsB[tx * 8 + 3], 0.f);
            o1.x = fmaxf(p2.x + bsB[tx * 8 + 4], 0.f);
            o1.y = fmaxf(p2.y + bsB[tx * 8 + 5], 0.f);
            o1.z = fmaxf(p3.x + bsB[tx * 8 + 6], 0.f);
            o1.w = fmaxf(p3.y + bsB[tx * 8 + 7], 0.f);
            float4* dst = (float4*)&out[(size_t)row * 128 + tx * 8];
            dst[0] = o0;
            dst[1] = o1;
        }
    }
}

// ---------------- y1 = x1 @ W2a  (projection BEFORE aggregation) ------------
#define Y1_SMEM_FLOATS (128 * 129 + 128 * 40)
__global__ __launch_bounds__(128) void y1_kernel(const float* __restrict__ W2a, int n) {
    extern __shared__ float sm[];
    float* As = sm;                  // 128 x 129 (padded)
    float* Wa = sm + 128 * 129;      // 128 x 40

    int tid = threadIdx.x;
    int row0 = blockIdx.x * 128;
    const float* A = g_x1;

    for (int i = tid; i < 128 * 32; i += 128) {
        int r = i >> 5, c = i & 31;
        float4 v = (row0 + r < n) ? ((const float4*)A)[(size_t)(row0 + r) * 32 + c]
                                  : make_float4(0.f, 0.f, 0.f, 0.f);
        float* d = &As[r * 129 + c * 4];
        d[0] = v.x; d[1] = v.y; d[2] = v.z; d[3] = v.w;
    }
    for (int i = tid; i < 128 * 10; i += 128)
        ((float4*)Wa)[i] = ((const float4*)W2a)[i];
    __syncthreads();

    unsigned long long h2[20];
#pragma unroll
    for (int c = 0; c < 20; c++) h2[c] = 0ull;
    const float* arow = &As[tid * 129];
#pragma unroll 4
    for (int k = 0; k < 128; k++) {
        float a = arow[k];
        unsigned long long a2 = pack2(a, a);
        const ulonglong2* w = (const ulonglong2*)&Wa[k * 40];
#pragma unroll
        for (int q = 0; q < 10; q++) {
            ulonglong2 wv = w[q];
            fma2(h2[q * 2 + 0], a2, wv.x);
            fma2(h2[q * 2 + 1], a2, wv.y);
        }
    }
#pragma unroll
    for (int c = 0; c < 20; c++) {
        float2 p = unpack2(h2[c]);
        As[tid * 129 + 2 * c + 0] = p.x;
        As[tid * 129 + 2 * c + 1] = p.y;
    }
    __syncthreads();
    for (int i = tid; i < 128 * 40; i += 128) {
        int r = i / 40, c = i - r * 40;
        int row = row0 + r;
        if (row < n) g_y1[(size_t)row * 40 + c] = As[r * 129 + c];
    }
}

// ---------------- agg2: warp per node, 40-dim gather (lanes 0-19, float2) ---
__global__ __launch_bounds__(256) void agg2_kernel(int n) {
    int gt = blockIdx.x * blockDim.x + threadIdx.x;
    int w = gt >> 5;
    int lane = gt & 31;
    if (w >= n || lane >= 20) return;
    const float2* y2 = (const float2*)g_y1;
    float2* o2 = (float2*)g_agg;  // reuse g_agg as aggy (100k x 40)
    float2 acc = y2[(size_t)w * 20 + lane];  // self term
    int s0 = g_offs[w], s1 = g_offs[w + 1];
    for (int j = s0; j < s1; j++) {
        int s = g_csr[j];
        float2 v = __ldg(&y2[(size_t)s * 20 + lane]);
        acc.x += v.x; acc.y += v.y;
    }
    o2[(size_t)w * 20 + lane] = acc;
}

// ---------------- final: out = softmax(relu(aggy + b2a) @ W2b + b2b) --------
#define G2B_ROWS 256
#define G2B_SMEM_FLOATS (G2B_ROWS * 41 + 40 * 40 + 40 + 40)
__global__ __launch_bounds__(256) void gemm2b_kernel(
    const float* __restrict__ b2a, const float* __restrict__ W2b,
    const float* __restrict__ b2b, float* __restrict__ out, int n) {
    extern __shared__ float sm[];
    float* As = sm;                       // 256 x 41 (padded)
    float* Wb = sm + G2B_ROWS * 41;       // 40 x 40
    float* ba = Wb + 40 * 40;             // 40
    float* bb = ba + 40;                  // 40

    int tid = threadIdx.x;
    int row0 = blockIdx.x * G2B_ROWS;
    const float* A = g_agg;  // aggy

    for (int i = tid; i < G2B_ROWS * 40; i += 256) {
        int r = i / 40, c = i - r * 40;
        int row = row0 + r;
        As[r * 41 + c] = (row < n) ? A[(size_t)row * 40 + c] : 0.f;
    }
    for (int i = tid; i < 1600; i += 256) Wb[i] = W2b[i];
    if (tid < 40) { ba[tid] = b2a[tid]; bb[tid] = b2b[tid]; }
    __syncthreads();

    float h[40];
    const float* arow = &As[tid * 41];
#pragma unroll
    for (int c = 0; c < 40; c++) h[c] = fmaxf(arow[c] + ba[c], 0.f);

    float o[40];
#pragma unroll
    for (int c = 0; c < 40; c++) o[c] = bb[c];
#pragma unroll 4
    for (int k = 0; k < 40; k++) {
        float a = h[k];
        const float4* w = (const float4*)&Wb[k * 40];
#pragma unroll
        for (int q = 0; q < 10; q++) {
            float4 wv = w[q];
            o[q * 4 + 0] = fmaf(a, wv.x, o[q * 4 + 0]);
            o[q * 4 + 1] = fmaf(a, wv.y, o[q * 4 + 1]);
            o[q * 4 + 2] = fmaf(a, wv.z, o[q * 4 + 2]);
            o[q * 4 + 3] = fmaf(a, wv.w, o[q * 4 + 3]);
        }
    }
    float mx = o[0];
#pragma unroll
    for (int c = 1; c < 40; c++) mx = fmaxf(mx, o[c]);
    float s = 0.f;
#pragma unroll
    for (int c = 0; c < 40; c++) { float e = __expf(o[c] - mx); o[c] = e; s += e; }
    float inv = 1.0f / s;
#pragma unroll
    for (int c = 0; c < 40; c++) As[tid * 41 + c] = o[c] * inv;
    __syncthreads();
    for (int i = tid; i < G2B_ROWS * 40; i += 256) {
        int r = i / 40, c = i - r * 40;
        int row = row0 + r;
        if (row < n) out[(size_t)row * 40 + c] = As[r * 41 + c];
    }
}

// ---------------- launcher --------------------------------------------------
extern "C" void kernel_launch(void* const* d_in, const int* in_sizes, int n_in,
                              void* d_out, int out_size) {
    int i_nodes = 0, i_edges = -1;
    for (int i = 1; i < n_in; i++)
        if (in_sizes[i] > in_sizes[i_nodes]) i_nodes = i;
    for (int i = 0; i < n_in; i++) {
        if (i == i_nodes) continue;
        if (i_edges < 0 || in_sizes[i] > in_sizes[i_edges]) i_edges = i;
    }

    const float* x0  = (const float*)d_in[i_nodes];
    const int2*  ei  = (const int2*)d_in[i_edges];
    int n = in_sizes[i_nodes] / DIM;
    int m = in_sizes[i_edges] / 2;

    const float *W1a = 0, *W1b = 0, *b1a = 0, *b1b = 0;
    const float *W2a = 0, *W2b = 0, *b2a = 0, *b2b = 0;
    for (int i = 0; i < n_in; i++) {
        if (i == i_nodes || i == i_edges) continue;
        int s = in_sizes[i];
        const float* p = (const float*)d_in[i];
        if (s == DIM * DIM)        { if (!W1a) W1a = p; else W1b = p; }
        else if (s == DIM)         { if (!b1a) b1a = p; else b1b = p; }
        else if (s == DIM * NCLS)  W2a = p;
        else if (s == NCLS * NCLS) W2b = p;
        else if (s == NCLS)        { if (!b2a) b2a = p; else b2b = p; }
    }
    float* out = (float*)d_out;

    const int g1_smem  = G1_SMEM_FLOATS * (int)sizeof(float);
    const int y1_smem  = Y1_SMEM_FLOATS * (int)sizeof(float);
    const int g2b_smem = G2B_SMEM_FLOATS * (int)sizeof(float);
    cudaFuncSetAttribute(gemm1_kernel, cudaFuncAttributeMaxDynamicSharedMemorySize, g1_smem);
    cudaFuncSetAttribute(y1_kernel, cudaFuncAttributeMaxDynamicSharedMemorySize, y1_smem);
    cudaFuncSetAttribute(gemm2b_kernel, cudaFuncAttributeMaxDynamicSharedMemorySize, g2b_smem);

    // CSR build (shared by both layers)
    zero_deg_kernel<<<(n + 255) / 256, 256>>>(n);
    hist_kernel<<<(m + 255) / 256, 256>>>(ei, m);
    scan_kernel<<<1, 1024>>>(n);
    fill_kernel<<<(m + 255) / 256, 256>>>(ei, m);

    // layer 1
    agg_kernel<<<((size_t)n * 32 + 255) / 256, 256>>>((const float4*)x0, n);
    gemm1_kernel<<<(n + 63) / 64, 256, g1_smem>>>(W1a, b1a, W1b, b1b, n);

    // layer 2 (project -> aggregate -> tiny GEMM + softmax)
    y1_kernel<<<(n + 127) / 128, 128, y1_smem>>>(W2a, n);
    agg2_kernel<<<((size_t)n * 32 + 255) / 256, 256>>>(n);
    gemm2b_kernel<<<(n + G2B_ROWS - 1) / G2B_ROWS, 256, g2b_smem>>>(b2a, W2b, b2b, out, n);
}

// round 8
// speedup vs baseline: 1.3675x; 1.2650x over previous
#include <cuda_runtime.h>
#include <math.h>

#define N_NODES_MAX 100000
#define N_EDGES_MAX 1600000
#define DIM 128
#define NCLS 40
#define SCB 4096  // elements per scan block

// ---------------- f32x2 packed-FMA helpers (sm_103a FFMA2) ------------------
__device__ __forceinline__ unsigned long long pack2(float lo, float hi) {
    unsigned long long v;
    asm("mov.b64 %0, {%1, %2};" : "=l"(v) : "f"(lo), "f"(hi));
    return v;
}
__device__ __forceinline__ float2 unpack2(unsigned long long v) {
    float2 r;
    asm("mov.b64 {%0, %1}, %2;" : "=f"(r.x), "=f"(r.y) : "l"(v));
    return r;
}
__device__ __forceinline__ void fma2(unsigned long long& d, unsigned long long a,
                                     unsigned long long b) {
    asm("fma.rn.f32x2 %0, %1, %2, %0;" : "+l"(d) : "l"(a), "l"(b));
}

// ---------------- scratch (static device allocations; no cudaMalloc) -------
__device__ int g_deg[N_NODES_MAX];
__device__ int g_offs[N_NODES_MAX + 1];
__device__ int g_cur[N_NODES_MAX];
__device__ int g_csr[N_EDGES_MAX];
__device__ int g_bsum[64];
__device__ int g_boff[64];
__device__ __align__(16) float g_agg[(size_t)N_NODES_MAX * DIM];   // also reused for aggy
__device__ __align__(16) float g_x1[(size_t)N_NODES_MAX * DIM];
__device__ __align__(16) float g_y1[(size_t)N_NODES_MAX * NCLS];

// ---------------- CSR build -------------------------------------------------
__global__ void zero_deg_kernel(int n) {
    int i = blockIdx.x * blockDim.x + threadIdx.x;
    if (i < n) g_deg[i] = 0;
}

__global__ void hist_kernel(const int2* __restrict__ e, int m) {
    int i = blockIdx.x * blockDim.x + threadIdx.x;
    if (i < m) atomicAdd(&g_deg[e[i].y], 1);
}

// ---- multi-block coalesced scan: A) per-block sums ----
__global__ __launch_bounds__(256) void scan_partial_kernel(int n) {
    __shared__ int s[SCB];
    __shared__ int ws[8];
    int base = blockIdx.x * SCB;
    int tid = threadIdx.x;
    for (int j = tid; j < SCB; j += 256)
        s[j] = (base + j < n) ? g_deg[base + j] : 0;
    __syncthreads();
    int mysum = 0;
#pragma unroll
    for (int j = 0; j < 16; j++) mysum += s[tid * 16 + j];
    int lane = tid & 31, wid = tid >> 5;
    int v = mysum;
#pragma unroll
    for (int o = 16; o > 0; o >>= 1) v += __shfl_down_sync(0xffffffffu, v, o);
    if (lane == 0) ws[wid] = v;
    __syncthreads();
    if (tid == 0) {
        int t = 0;
#pragma unroll
        for (int i = 0; i < 8; i++) t += ws[i];
        g_bsum[blockIdx.x] = t;
    }
}

// ---- B) 1-warp scan of block sums; writes g_offs[n] = grand total ----
__global__ void scan_tops_kernel(int nb, int n) {
    int t = threadIdx.x;  // 32 threads
    int x = (t < nb) ? g_bsum[t] : 0;
    int v = x;
#pragma unroll
    for (int o = 1; o < 32; o <<= 1) {
        int u = __shfl_up_sync(0xffffffffu, v, o);
        if (t >= o) v += u;
    }
    if (t < nb) g_boff[t] = v - x;      // exclusive
    if (t == 31) g_offs[n] = v;         // inclusive over all (nb <= 32)
}

// ---- C) per-block scan + coalesced offs/cur stores ----
__global__ __launch_bounds__(256) void scan_final_kernel(int n) {
    __shared__ int s[SCB];
    __shared__ int ws[8];
    int base = blockIdx.x * SCB;
    int tid = threadIdx.x;
    for (int j = tid; j < SCB; j += 256)
        s[j] = (base + j < n) ? g_deg[base + j] : 0;
    __syncthreads();
    int mysum = 0;
#pragma unroll
    for (int j = 0; j < 16; j++) mysum += s[tid * 16 + j];
    int lane = tid & 31, wid = tid >> 5;
    int v = mysum;
#pragma unroll
    for (int o = 1; o < 32; o <<= 1) {
        int u = __shfl_up_sync(0xffffffffu, v, o);
        if (lane >= o) v += u;
    }
    if (lane == 31) ws[wid] = v;
    __syncthreads();
    if (wid == 0 && lane < 8) {
        int w = ws[lane];
#pragma unroll
        for (int o = 1; o < 8; o <<= 1) {
            int u = __shfl_up_sync(0xffu, w, o);
            if (lane >= o) w += u;
        }
        ws[lane] = w;
    }
    __syncthreads();
    int run = (v - mysum) + ((wid > 0) ? ws[wid - 1] : 0) + g_boff[blockIdx.x];
#pragma unroll
    for (int j = 0; j < 16; j++) {
        int idx = tid * 16 + j;
        int t = s[idx];
        s[idx] = run;
        run += t;
    }
    __syncthreads();
    for (int j = tid; j < SCB; j += 256) {
        int gi = base + j;
        if (gi < n) { g_offs[gi] = s[j]; g_cur[gi] = s[j]; }
    }
}

__global__ void fill_kernel(const int2* __restrict__ e, int m) {
    int i = blockIdx.x * blockDim.x + threadIdx.x;
    if (i < m) {
        int2 ed = e[i];
        int p = atomicAdd(&g_cur[ed.y], 1);
        g_csr[p] = ed.x;
    }
}

// ---------------- agg1: warp per node, 128-dim gather -----------------------
__global__ __launch_bounds__(256) void agg_kernel(const float4* __restrict__ x4, int n) {
    int gt = blockIdx.x * blockDim.x + threadIdx.x;
    int w = gt >> 5;
    int lane = gt & 31;
    if (w >= n) return;
    float4* o4 = (float4*)g_agg;
    float4 acc = x4[(size_t)w * 32 + lane];
    int s0 = g_offs[w], s1 = g_offs[w + 1];
    for (int j = s0; j < s1; j++) {
        int s = g_csr[j];
        float4 v = __ldg(&x4[(size_t)s * 32 + lane]);
        acc.x += v.x; acc.y += v.y; acc.z += v.z; acc.w += v.w;
    }
    o4[(size_t)w * 32 + lane] = acc;
}

// ---------------- layer 1: x1 = relu(relu(agg@W1a+b1a)@W1b + b1b) -----------
#define G1_SMEM_FLOATS (64 * 129 + 128 * 128 + 128 + 128)
__global__ __launch_bounds__(256) void gemm1_kernel(
    const float* __restrict__ W1a, const float* __restrict__ b1a,
    const float* __restrict__ W1b, const float* __restrict__ b1b, int n) {
    extern __shared__ float sm[];
    float* As = sm;                    // 64 x 129 (padded)
    float* Wsh = sm + 64 * 129;        // 128 x 128
    float* bsA = Wsh + 128 * 128;      // 128
    float* bsB = bsA + 128;            // 128

    int tid = threadIdx.x;
    int tx = tid & 15, ty = tid >> 4;
    int row0 = blockIdx.x * 64;
    const float* A = g_agg;
    float* out = g_x1;

    for (int i = tid; i < 64 * 32; i += 256) {
        int r = i >> 5, c = i & 31;
        float4 v = (row0 + r < n) ? ((const float4*)A)[(size_t)(row0 + r) * 32 + c]
                                  : make_float4(0.f, 0.f, 0.f, 0.f);
        float* d = &As[r * 129 + c * 4];
        d[0] = v.x; d[1] = v.y; d[2] = v.z; d[3] = v.w;
    }
    for (int i = tid; i < 128 * 32; i += 256)
        ((float4*)Wsh)[i] = ((const float4*)W1a)[i];
    if (tid < 128) { bsA[tid] = b1a[tid]; bsB[tid] = b1b[tid]; }
    __syncthreads();

    unsigned long long acc2[4][4];
#pragma unroll
    for (int r = 0; r < 4; r++)
#pragma unroll
        for (int c = 0; c < 4; c++) acc2[r][c] = 0ull;

    const float* a0 = &As[(ty * 4) * 129];
#pragma unroll 8
    for (int k = 0; k < 128; k++) {
        unsigned long long av2[4];
#pragma unroll
        for (int r = 0; r < 4; r++) {
            float a = a0[r * 129 + k];
            av2[r] = pack2(a, a);
        }
        const ulonglong2* wp = (const ulonglong2*)&Wsh[k * 128 + tx * 8];
        ulonglong2 wA = wp[0];
        ulonglong2 wB = wp[1];
#pragma unroll
        for (int r = 0; r < 4; r++) {
            fma2(acc2[r][0], av2[r], wA.x);
            fma2(acc2[r][1], av2[r], wA.y);
            fma2(acc2[r][2], av2[r], wB.x);
            fma2(acc2[r][3], av2[r], wB.y);
        }
    }
    __syncthreads();

#pragma unroll
    for (int r = 0; r < 4; r++)
#pragma unroll
        for (int c = 0; c < 4; c++) {
            float2 p = unpack2(acc2[r][c]);
            As[(ty * 4 + r) * 129 + tx * 8 + 2 * c + 0] = fmaxf(p.x + bsA[tx * 8 + 2 * c + 0], 0.f);
            As[(ty * 4 + r) * 129 + tx * 8 + 2 * c + 1] = fmaxf(p.y + bsA[tx * 8 + 2 * c + 1], 0.f);
            acc2[r][c] = 0ull;
        }
    for (int i = tid; i < 128 * 32; i += 256)
        ((float4*)Wsh)[i] = ((const float4*)W1b)[i];
    __syncthreads();

#pragma unroll 8
    for (int k = 0; k < 128; k++) {
        unsigned long long av2[4];
#pragma unroll
        for (int r = 0; r < 4; r++) {
            float a = a0[r * 129 + k];
            av2[r] = pack2(a, a);
        }
        const ulonglong2* wp = (const ulonglong2*)&Wsh[k * 128 + tx * 8];
        ulonglong2 wA = wp[0];
        ulonglong2 wB = wp[1];
#pragma unroll
        for (int r = 0; r < 4; r++) {
            fma2(acc2[r][0], av2[r], wA.x);
            fma2(acc2[r][1], av2[r], wA.y);
            fma2(acc2[r][2], av2[r], wB.x);
            fma2(acc2[r][3], av2[r], wB.y);
        }
    }

#pragma unroll
    for (int r = 0; r < 4; r++) {
        int row = row0 + ty * 4 + r;
        if (row < n) {
            float2 p0 = unpack2(acc2[r][0]);
            float2 p1 = unpack2(acc2[r][1]);
            float2 p2 = unpack2(acc2[r][2]);
            float2 p3 = unpack2(acc2[r][3]);
            float4 o0, o1;
            o0.x = fmaxf(p0.x + bsB[tx * 8 + 0], 0.f);
            o0.y = fmaxf(p0.y + bsB[tx * 8 + 1], 0.f);
            o0.z = fmaxf(p1.x + bsB[tx * 8 + 2], 0.f);
            o0.w = fmaxf(p1.y + bsB[tx * 8 + 3], 0.f);
            o1.x = fmaxf(p2.x + bsB[tx * 8 + 4], 0.f);
            o1.y = fmaxf(p2.y + bsB[tx * 8 + 5], 0.f);
            o1.z = fmaxf(p3.x + bsB[tx * 8 + 6], 0.f);
            o1.w = fmaxf(p3.y + bsB[tx * 8 + 7], 0.f);
            float4* dst = (float4*)&out[(size_t)row * 128 + tx * 8];
            dst[0] = o0;
            dst[1] = o1;
        }
    }
}

// ---------------- y1 = x1 @ W2a  (projection BEFORE aggregation) ------------
#define Y1_SMEM_FLOATS (128 * 129 + 128 * 40)
__global__ __launch_bounds__(128) void y1_kernel(const float* __restrict__ W2a, int n) {
    extern __shared__ float sm[];
    float* As = sm;                  // 128 x 129 (padded)
    float* Wa = sm + 128 * 129;      // 128 x 40

    int tid = threadIdx.x;
    int row0 = blockIdx.x * 128;
    const float* A = g_x1;

    for (int i = tid; i < 128 * 32; i += 128) {
        int r = i >> 5, c = i & 31;
        float4 v = (row0 + r < n) ? ((const float4*)A)[(size_t)(row0 + r) * 32 + c]
                                  : make_float4(0.f, 0.f, 0.f, 0.f);
        float* d = &As[r * 129 + c * 4];
        d[0] = v.x; d[1] = v.y; d[2] = v.z; d[3] = v.w;
    }
    for (int i = tid; i < 128 * 10; i += 128)
        ((float4*)Wa)[i] = ((const float4*)W2a)[i];
    __syncthreads();

    unsigned long long h2[20];
#pragma unroll
    for (int c = 0; c < 20; c++) h2[c] = 0ull;
    const float* arow = &As[tid * 129];
#pragma unroll 4
    for (int k = 0; k < 128; k++) {
        float a = arow[k];
        unsigned long long a2 = pack2(a, a);
        const ulonglong2* w = (const ulonglong2*)&Wa[k * 40];
#pragma unroll
        for (int q = 0; q < 10; q++) {
            ulonglong2 wv = w[q];
            fma2(h2[q * 2 + 0], a2, wv.x);
            fma2(h2[q * 2 + 1], a2, wv.y);
        }
    }
#pragma unroll
    for (int c = 0; c < 20; c++) {
        float2 p = unpack2(h2[c]);
        As[tid * 129 + 2 * c + 0] = p.x;
        As[tid * 129 + 2 * c + 1] = p.y;
    }
    __syncthreads();
    for (int i = tid; i < 128 * 40; i += 128) {
        int r = i / 40, c = i - r * 40;
        int row = row0 + r;
        if (row < n) g_y1[(size_t)row * 40 + c] = As[r * 129 + c];
    }
}

// ---------------- agg2: warp per node, 40-dim gather (lanes 0-19, float2) ---
__global__ __launch_bounds__(256) void agg2_kernel(int n) {
    int gt = blockIdx.x * blockDim.x + threadIdx.x;
    int w = gt >> 5;
    int lane = gt & 31;
    if (w >= n || lane >= 20) return;
    const float2* y2 = (const float2*)g_y1;
    float2* o2 = (float2*)g_agg;
    float2 acc = y2[(size_t)w * 20 + lane];
    int s0 = g_offs[w], s1 = g_offs[w + 1];
    for (int j = s0; j < s1; j++) {
        int s = g_csr[j];
        float2 v = __ldg(&y2[(size_t)s * 20 + lane]);
        acc.x += v.x; acc.y += v.y;
    }
    o2[(size_t)w * 20 + lane] = acc;
}

// ---------------- final: out = softmax(relu(aggy + b2a) @ W2b + b2b) --------
#define G2B_ROWS 256
#define G2B_SMEM_FLOATS (G2B_ROWS * 41 + 40 * 40 + 40 + 40)
__global__ __launch_bounds__(256) void gemm2b_kernel(
    const float* __restrict__ b2a, const float* __restrict__ W2b,
    const float* __restrict__ b2b, float* __restrict__ out, int n) {
    extern __shared__ float sm[];
    float* As = sm;
    float* Wb = sm + G2B_ROWS * 41;
    float* ba = Wb + 40 * 40;
    float* bb = ba + 40;

    int tid = threadIdx.x;
    int row0 = blockIdx.x * G2B_ROWS;
    const float* A = g_agg;

    for (int i = tid; i < G2B_ROWS * 40; i += 256) {
        int r = i / 40, c = i - r * 40;
        int row = row0 + r;
        As[r * 41 + c] = (row < n) ? A[(size_t)row * 40 + c] : 0.f;
    }
    for (int i = tid; i < 1600; i += 256) Wb[i] = W2b[i];
    if (tid < 40) { ba[tid] = b2a[tid]; bb[tid] = b2b[tid]; }
    __syncthreads();

    float h[40];
    const float* arow = &As[tid * 41];
#pragma unroll
    for (int c = 0; c < 40; c++) h[c] = fmaxf(arow[c] + ba[c], 0.f);

    float o[40];
#pragma unroll
    for (int c = 0; c < 40; c++) o[c] = bb[c];
#pragma unroll 4
    for (int k = 0; k < 40; k++) {
        float a = h[k];
        const float4* w = (const float4*)&Wb[k * 40];
#pragma unroll
        for (int q = 0; q < 10; q++) {
            float4 wv = w[q];
            o[q * 4 + 0] = fmaf(a, wv.x, o[q * 4 + 0]);
            o[q * 4 + 1] = fmaf(a, wv.y, o[q * 4 + 1]);
            o[q * 4 + 2] = fmaf(a, wv.z, o[q * 4 + 2]);
            o[q * 4 + 3] = fmaf(a, wv.w, o[q * 4 + 3]);
        }
    }
    float mx = o[0];
#pragma unroll
    for (int c = 1; c < 40; c++) mx = fmaxf(mx, o[c]);
    float s = 0.f;
#pragma unroll
    for (int c = 0; c < 40; c++) { float e = __expf(o[c] - mx); o[c] = e; s += e; }
    float inv = 1.0f / s;
#pragma unroll
    for (int c = 0; c < 40; c++) As[tid * 41 + c] = o[c] * inv;
    __syncthreads();
    for (int i = tid; i < G2B_ROWS * 40; i += 256) {
        int r = i / 40, c = i - r * 40;
        int row = row0 + r;
        if (row < n) out[(size_t)row * 40 + c] = As[r * 41 + c];
    }
}

// ---------------- launcher --------------------------------------------------
extern "C" void kernel_launch(void* const* d_in, const int* in_sizes, int n_in,
                              void* d_out, int out_size) {
    int i_nodes = 0, i_edges = -1;
    for (int i = 1; i < n_in; i++)
        if (in_sizes[i] > in_sizes[i_nodes]) i_nodes = i;
    for (int i = 0; i < n_in; i++) {
        if (i == i_nodes) continue;
        if (i_edges < 0 || in_sizes[i] > in_sizes[i_edges]) i_edges = i;
    }

    const float* x0  = (const float*)d_in[i_nodes];
    const int2*  ei  = (const int2*)d_in[i_edges];
    int n = in_sizes[i_nodes] / DIM;
    int m = in_sizes[i_edges] / 2;

    const float *W1a = 0, *W1b = 0, *b1a = 0, *b1b = 0;
    const float *W2a = 0, *W2b = 0, *b2a = 0, *b2b = 0;
    for (int i = 0; i < n_in; i++) {
        if (i == i_nodes || i == i_edges) continue;
        int s = in_sizes[i];
        const float* p = (const float*)d_in[i];
        if (s == DIM * DIM)        { if (!W1a) W1a = p; else W1b = p; }
        else if (s == DIM)         { if (!b1a) b1a = p; else b1b = p; }
        else if (s == DIM * NCLS)  W2a = p;
        else if (s == NCLS * NCLS) W2b = p;
        else if (s == NCLS)        { if (!b2a) b2a = p; else b2b = p; }
    }
    float* out = (float*)d_out;

    const int g1_smem  = G1_SMEM_FLOATS * (int)sizeof(float);
    const int y1_smem  = Y1_SMEM_FLOATS * (int)sizeof(float);
    const int g2b_smem = G2B_SMEM_FLOATS * (int)sizeof(float);
    cudaFuncSetAttribute(gemm1_kernel, cudaFuncAttributeMaxDynamicSharedMemorySize, g1_smem);
    cudaFuncSetAttribute(y1_kernel, cudaFuncAttributeMaxDynamicSharedMemorySize, y1_smem);
    cudaFuncSetAttribute(gemm2b_kernel, cudaFuncAttributeMaxDynamicSharedMemorySize, g2b_smem);

    int nb = (n + SCB - 1) / SCB;  // 25 for n=100k (<= 32 required by scan_tops)

    // CSR build (shared by both layers) — multi-block coalesced scan
    zero_deg_kernel<<<(n + 255) / 256, 256>>>(n);
    hist_kernel<<<(m + 255) / 256, 256>>>(ei, m);
    scan_partial_kernel<<<nb, 256>>>(n);
    scan_tops_kernel<<<1, 32>>>(nb, n);
    scan_final_kernel<<<nb, 256>>>(n);
    fill_kernel<<<(m + 255) / 256, 256>>>(ei, m);

    // layer 1
    agg_kernel<<<((size_t)n * 32 + 255) / 256, 256>>>((const float4*)x0, n);
    gemm1_kernel<<<(n + 63) / 64, 256, g1_smem>>>(W1a, b1a, W1b, b1b, n);

    // layer 2 (project -> aggregate -> tiny GEMM + softmax)
    y1_kernel<<<(n + 127) / 128, 128, y1_smem>>>(W2a, n);
    agg2_kernel<<<((size_t)n * 32 + 255) / 256, 256>>>(n);
    gemm2b_kernel<<<(n + G2B_ROWS - 1) / G2B_ROWS, 256, g2b_smem>>>(b2a, W2b, b2b, out, n);
}

// round 11
// speedup vs baseline: 2.1558x; 1.5765x over previous
#include <cuda_runtime.h>
#include <cuda_bf16.h>
#include <math.h>

#define N_NODES_MAX 100000
#define N_EDGES_MAX 1600000
#define DIM 128
#define NCLS 40
#define SCB 4096  // elements per scan block

// ---------------- f32x2 packed-FMA helpers (kept for y1) --------------------
__device__ __forceinline__ unsigned long long pack2(float lo, float hi) {
    unsigned long long v;
    asm("mov.b64 %0, {%1, %2};" : "=l"(v) : "f"(lo), "f"(hi));
    return v;
}
__device__ __forceinline__ float2 unpack2(unsigned long long v) {
    float2 r;
    asm("mov.b64 {%0, %1}, %2;" : "=f"(r.x), "=f"(r.y) : "l"(v));
    return r;
}
__device__ __forceinline__ void fma2(unsigned long long& d, unsigned long long a,
                                     unsigned long long b) {
    asm("fma.rn.f32x2 %0, %1, %2, %0;" : "+l"(d) : "l"(a), "l"(b));
}

// ---------------- bf16 split helpers ----------------------------------------
__device__ __forceinline__ unsigned pack_bf2(__nv_bfloat16 a, __nv_bfloat16 b) {
    __nv_bfloat162 t;
    t.x = a; t.y = b;
    return *reinterpret_cast<unsigned*>(&t);
}
// split f into hi (bf16) and residual lo (bf16)
__device__ __forceinline__ void split_bf(float f, __nv_bfloat16& hi, __nv_bfloat16& lo) {
    hi = __float2bfloat16_rn(f);
    lo = __float2bfloat16_rn(f - __bfloat162float(hi));
}
__device__ __forceinline__ void mma_bf16(float* c, unsigned a0, unsigned a1,
                                         unsigned a2, unsigned a3,
                                         unsigned b0, unsigned b1) {
    asm volatile(
        "mma.sync.aligned.m16n8k16.row.col.f32.bf16.bf16.f32 "
        "{%0,%1,%2,%3}, {%4,%5,%6,%7}, {%8,%9}, {%0,%1,%2,%3};"
        : "+f"(c[0]), "+f"(c[1]), "+f"(c[2]), "+f"(c[3])
        : "r"(a0), "r"(a1), "r"(a2), "r"(a3), "r"(b0), "r"(b1));
}

// ---------------- scratch (static device allocations; no cudaMalloc) -------
__device__ int g_deg[N_NODES_MAX];
__device__ int g_offs[N_NODES_MAX + 1];
__device__ int g_cur[N_NODES_MAX];
__device__ int g_csr[N_EDGES_MAX];
__device__ int g_bsum[64];
__device__ int g_boff[64];
__device__ __align__(16) float g_agg[(size_t)N_NODES_MAX * DIM];   // also reused for aggy
__device__ __align__(16) float g_x1[(size_t)N_NODES_MAX * DIM];
__device__ __align__(16) float g_y1[(size_t)N_NODES_MAX * NCLS];

// ---------------- CSR build -------------------------------------------------
__global__ void zero_deg_kernel(int n) {
    int i = blockIdx.x * blockDim.x + threadIdx.x;
    if (i < n) g_deg[i] = 0;
}

__global__ void hist_kernel(const int2* __restrict__ e, int m) {
    int i = blockIdx.x * blockDim.x + threadIdx.x;
    if (i < m) atomicAdd(&g_deg[e[i].y], 1);
}

__global__ __launch_bounds__(256) void scan_partial_kernel(int n) {
    __shared__ int s[SCB];
    __shared__ int ws[8];
    int base = blockIdx.x * SCB;
    int tid = threadIdx.x;
    for (int j = tid; j < SCB; j += 256)
        s[j] = (base + j < n) ? g_deg[base + j] : 0;
    __syncthreads();
    int mysum = 0;
#pragma unroll
    for (int j = 0; j < 16; j++) mysum += s[tid * 16 + j];
    int lane = tid & 31, wid = tid >> 5;
    int v = mysum;
#pragma unroll
    for (int o = 16; o > 0; o >>= 1) v += __shfl_down_sync(0xffffffffu, v, o);
    if (lane == 0) ws[wid] = v;
    __syncthreads();
    if (tid == 0) {
        int t = 0;
#pragma unroll
        for (int i = 0; i < 8; i++) t += ws[i];
        g_bsum[blockIdx.x] = t;
    }
}

__global__ void scan_tops_kernel(int nb, int n) {
    int t = threadIdx.x;  // 32 threads
    int x = (t < nb) ? g_bsum[t] : 0;
    int v = x;
#pragma unroll
    for (int o = 1; o < 32; o <<= 1) {
        int u = __shfl_up_sync(0xffffffffu, v, o);
        if (t >= o) v += u;
    }
    if (t < nb) g_boff[t] = v - x;
    if (t == 31) g_offs[n] = v;
}

__global__ __launch_bounds__(256) void scan_final_kernel(int n) {
    __shared__ int s[SCB];
    __shared__ int ws[8];
    int base = blockIdx.x * SCB;
    int tid = threadIdx.x;
    for (int j = tid; j < SCB; j += 256)
        s[j] = (base + j < n) ? g_deg[base + j] : 0;
    __syncthreads();
    int mysum = 0;
#pragma unroll
    for (int j = 0; j < 16; j++) mysum += s[tid * 16 + j];
    int lane = tid & 31, wid = tid >> 5;
    int v = mysum;
#pragma unroll
    for (int o = 1; o < 32; o <<= 1) {
        int u = __shfl_up_sync(0xffffffffu, v, o);
        if (lane >= o) v += u;
    }
    if (lane == 31) ws[wid] = v;
    __syncthreads();
    if (wid == 0 && lane < 8) {
        int w = ws[lane];
#pragma unroll
        for (int o = 1; o < 8; o <<= 1) {
            int u = __shfl_up_sync(0xffu, w, o);
            if (lane >= o) w += u;
        }
        ws[lane] = w;
    }
    __syncthreads();
    int run = (v - mysum) + ((wid > 0) ? ws[wid - 1] : 0) + g_boff[blockIdx.x];
#pragma unroll
    for (int j = 0; j < 16; j++) {
        int idx = tid * 16 + j;
        int t = s[idx];
        s[idx] = run;
        run += t;
    }
    __syncthreads();
    for (int j = tid; j < SCB; j += 256) {
        int gi = base + j;
        if (gi < n) { g_offs[gi] = s[j]; g_cur[gi] = s[j]; }
    }
}

__global__ void fill_kernel(const int2* __restrict__ e, int m) {
    int i = blockIdx.x * blockDim.x + threadIdx.x;
    if (i < m) {
        int2 ed = e[i];
        int p = atomicAdd(&g_cur[ed.y], 1);
        g_csr[p] = ed.x;
    }
}

// ---------------- agg1: warp per node, 128-dim gather -----------------------
__global__ __launch_bounds__(256) void agg_kernel(const float4* __restrict__ x4, int n) {
    int gt = blockIdx.x * blockDim.x + threadIdx.x;
    int w = gt >> 5;
    int lane = gt & 31;
    if (w >= n) return;
    float4* o4 = (float4*)g_agg;
    float4 acc = x4[(size_t)w * 32 + lane];
    int s0 = g_offs[w], s1 = g_offs[w + 1];
    for (int j = s0; j < s1; j++) {
        int s = g_csr[j];
        float4 v = __ldg(&x4[(size_t)s * 32 + lane]);
        acc.x += v.x; acc.y += v.y; acc.z += v.z; acc.w += v.w;
    }
    o4[(size_t)w * 32 + lane] = acc;
}

// ---------------- layer 1 via split-bf16 tensor-core MMA --------------------
// x1 = relu(relu(agg@W1a+b1a)@W1b + b1b), both phases in one kernel.
// f32 operands split into bf16 hi+lo; product = hi*hi + hi*lo + lo*hi.
// smem word layout (4B words):
//   A2H[64][68], A2L[64][68]      : A/H tile, bf16x2 k-pairs, stride 68
//   WTH[128][68], WTL[128][68]    : W^T tile (n-major), bf16x2 k-pairs
//   BSA[128], BSB[128]            : biases (float)
#define SAW 68
#define OFF_A2H 0
#define OFF_A2L (OFF_A2H + 64 * SAW)
#define OFF_WTH (OFF_A2L + 64 * SAW)
#define OFF_WTL (OFF_WTH + 128 * SAW)
#define OFF_BSA (OFF_WTL + 128 * SAW)
#define OFF_BSB (OFF_BSA + 128)
#define G1_SMEM_WORDS (OFF_BSB + 128)
#define G1_SMEM_BYTES (G1_SMEM_WORDS * 4)

__device__ __forceinline__ void g1_convert_W(unsigned* WTH, unsigned* WTL,
                                             const float* __restrict__ W, int tid) {
    // W row-major [k][n] -> WT n-major bf16x2 pairs [n][kpair]
    for (int i = tid; i < 64 * 128; i += 256) {
        int kp = i >> 7;       // k-pair 0..63
        int nn = i & 127;      // n 0..127 (lanes consecutive -> coalesced LDG)
        float f0 = W[(2 * kp) * 128 + nn];
        float f1 = W[(2 * kp + 1) * 128 + nn];
        __nv_bfloat16 h0, l0, h1, l1;
        split_bf(f0, h0, l0);
        split_bf(f1, h1, l1);
        WTH[nn * SAW + kp] = pack_bf2(h0, h1);
        WTL[nn * SAW + kp] = pack_bf2(l0, l1);
    }
}

__global__ __launch_bounds__(256) void gemm1_kernel(
    const float* __restrict__ W1a, const float* __restrict__ b1a,
    const float* __restrict__ W1b, const float* __restrict__ b1b, int n) {
    extern __shared__ unsigned su[];
    unsigned* A2H = su + OFF_A2H;
    unsigned* A2L = su + OFF_A2L;
    unsigned* WTH = su + OFF_WTH;
    unsigned* WTL = su + OFF_WTL;
    float* bsA = (float*)(su + OFF_BSA);
    float* bsB = (float*)(su + OFF_BSB);

    int tid = threadIdx.x;
    int lane = tid & 31, wid = tid >> 5;
    int r0 = (wid >> 1) << 4;   // warp row base (0,16,32,48)
    int n0 = (wid & 1) << 6;    // warp col base (0,64)
    int row0 = blockIdx.x * 64;

    // stage A tile (convert f32 -> bf16 hi/lo pairs)
    for (int i = tid; i < 64 * 32; i += 256) {
        int r = i >> 5, c = i & 31;  // c = float4 index
        float4 v = (row0 + r < n) ? ((const float4*)g_agg)[(size_t)(row0 + r) * 32 + c]
                                  : make_float4(0.f, 0.f, 0.f, 0.f);
        __nv_bfloat16 hx, lx, hy, ly, hz, lz, hw, lw;
        split_bf(v.x, hx, lx); split_bf(v.y, hy, ly);
        split_bf(v.z, hz, lz); split_bf(v.w, hw, lw);
        A2H[r * SAW + 2 * c + 0] = pack_bf2(hx, hy);
        A2H[r * SAW + 2 * c + 1] = pack_bf2(hz, hw);
        A2L[r * SAW + 2 * c + 0] = pack_bf2(lx, ly);
        A2L[r * SAW + 2 * c + 1] = pack_bf2(lz, lw);
    }
    g1_convert_W(WTH, WTL, W1a, tid);
    if (tid < 128) { bsA[tid] = b1a[tid]; bsB[tid] = b1b[tid]; }
    __syncthreads();

    float acc[8][4];
#pragma unroll
    for (int t = 0; t < 8; t++)
#pragma unroll
        for (int q = 0; q < 4; q++) acc[t][q] = 0.f;

    int arow = (r0 + (lane >> 2)) * SAW + (lane & 3);
    // ---------------- phase 1 mma ----------------
    for (int kk = 0; kk < 8; kk++) {
        int aw = arow + kk * 8;
        unsigned ah0 = A2H[aw], ah1 = A2H[aw + 8 * SAW];
        unsigned ah2 = A2H[aw + 4], ah3 = A2H[aw + 8 * SAW + 4];
        unsigned al0 = A2L[aw], al1 = A2L[aw + 8 * SAW];
        unsigned al2 = A2L[aw + 4], al3 = A2L[aw + 8 * SAW + 4];
#pragma unroll
        for (int t = 0; t < 8; t++) {
            int bw = (n0 + t * 8 + (lane >> 2)) * SAW + kk * 8 + (lane & 3);
            unsigned bh0 = WTH[bw], bh1 = WTH[bw + 4];
            unsigned bl0 = WTL[bw], bl1 = WTL[bw + 4];
            mma_bf16(acc[t], ah0, ah1, ah2, ah3, bh0, bh1);
            mma_bf16(acc[t], ah0, ah1, ah2, ah3, bl0, bl1);
            mma_bf16(acc[t], al0, al1, al2, al3, bh0, bh1);
        }
    }
    __syncthreads();  // all phase-1 reads of A2/WT done

    // epilogue 1: H = relu(acc + b1a) -> A2 (hi/lo); load W1b
    {
        int row = r0 + (lane >> 2);
#pragma unroll
        for (int t = 0; t < 8; t++) {
            int col = n0 + t * 8 + (lane & 3) * 2;
            int pair = col >> 1;
            float h00 = fmaxf(acc[t][0] + bsA[col], 0.f);
            float h01 = fmaxf(acc[t][1] + bsA[col + 1], 0.f);
            float h10 = fmaxf(acc[t][2] + bsA[col], 0.f);
            float h11 = fmaxf(acc[t][3] + bsA[col + 1], 0.f);
            __nv_bfloat16 h, l, h2, l2;
            split_bf(h00, h, l); split_bf(h01, h2, l2);
            A2H[row * SAW + pair] = pack_bf2(h, h2);
            A2L[row * SAW + pair] = pack_bf2(l, l2);
            split_bf(h10, h, l); split_bf(h11, h2, l2);
            A2H[(row + 8) * SAW + pair] = pack_bf2(h, h2);
            A2L[(row + 8) * SAW + pair] = pack_bf2(l, l2);
            acc[t][0] = acc[t][1] = acc[t][2] = acc[t][3] = 0.f;
        }
    }
    g1_convert_W(WTH, WTL, W1b, tid);
    __syncthreads();

    // ---------------- phase 2 mma ----------------
    for (int kk = 0; kk < 8; kk++) {
        int aw = arow + kk * 8;
        unsigned ah0 = A2H[aw], ah1 = A2H[aw + 8 * SAW];
        unsigned ah2 = A2H[aw + 4], ah3 = A2H[aw + 8 * SAW + 4];
        unsigned al0 = A2L[aw], al1 = A2L[aw + 8 * SAW];
        unsigned al2 = A2L[aw + 4], al3 = A2L[aw + 8 * SAW + 4];
#pragma unroll
        for (int t = 0; t < 8; t++) {
            int bw = (n0 + t * 8 + (lane >> 2)) * SAW + kk * 8 + (lane & 3);
            unsigned bh0 = WTH[bw], bh1 = WTH[bw + 4];
            unsigned bl0 = WTL[bw], bl1 = WTL[bw + 4];
            mma_bf16(acc[t], ah0, ah1, ah2, ah3, bh0, bh1);
            mma_bf16(acc[t], ah0, ah1, ah2, ah3, bl0, bl1);
            mma_bf16(acc[t], al0, al1, al2, al3, bh0, bh1);
        }
    }

    // final: x1 = relu(acc + b1b)
    {
        int row = row0 + r0 + (lane >> 2);
#pragma unroll
        for (int t = 0; t < 8; t++) {
            int col = n0 + t * 8 + (lane & 3) * 2;
            if (row < n) {
                float2 o;
                o.x = fmaxf(acc[t][0] + bsB[col], 0.f);
                o.y = fmaxf(acc[t][1] + bsB[col + 1], 0.f);
                *(float2*)&g_x1[(size_t)row * 128 + col] = o;
            }
            if (row + 8 < n) {
                float2 o;
                o.x = fmaxf(acc[t][2] + bsB[col], 0.f);
                o.y = fmaxf(acc[t][3] + bsB[col + 1], 0.f);
                *(float2*)&g_x1[(size_t)(row + 8) * 128 + col] = o;
            }
        }
    }
}

// ---------------- y1 = x1 @ W2a  (projection BEFORE aggregation) ------------
#define Y1_SMEM_FLOATS (128 * 129 + 128 * 40)
__global__ __launch_bounds__(128) void y1_kernel(const float* __restrict__ W2a, int n) {
    extern __shared__ float sm[];
    float* As = sm;
    float* Wa = sm + 128 * 129;

    int tid = threadIdx.x;
    int row0 = blockIdx.x * 128;
    const float* A = g_x1;

    for (int i = tid; i < 128 * 32; i += 128) {
        int r = i >> 5, c = i & 31;
        float4 v = (row0 + r < n) ? ((const float4*)A)[(size_t)(row0 + r) * 32 + c]
                                  : make_float4(0.f, 0.f, 0.f, 0.f);
        float* d = &As[r * 129 + c * 4];
        d[0] = v.x; d[1] = v.y; d[2] = v.z; d[3] = v.w;
    }
    for (int i = tid; i < 128 * 10; i += 128)
        ((float4*)Wa)[i] = ((const float4*)W2a)[i];
    __syncthreads();

    unsigned long long h2[20];
#pragma unroll
    for (int c = 0; c < 20; c++) h2[c] = 0ull;
    const float* arow = &As[tid * 129];
#pragma unroll 4
    for (int k = 0; k < 128; k++) {
        float a = arow[k];
        unsigned long long a2 = pack2(a, a);
        const ulonglong2* w = (const ulonglong2*)&Wa[k * 40];
#pragma unroll
        for (int q = 0; q < 10; q++) {
            ulonglong2 wv = w[q];
            fma2(h2[q * 2 + 0], a2, wv.x);
            fma2(h2[q * 2 + 1], a2, wv.y);
        }
    }
#pragma unroll
    for (int c = 0; c < 20; c++) {
        float2 p = unpack2(h2[c]);
        As[tid * 129 + 2 * c + 0] = p.x;
        As[tid * 129 + 2 * c + 1] = p.y;
    }
    __syncthreads();
    for (int i = tid; i < 128 * 40; i += 128) {
        int r = i / 40, c = i - r * 40;
        int row = row0 + r;
        if (row < n) g_y1[(size_t)row * 40 + c] = As[r * 129 + c];
    }
}

// ---------------- agg2: warp per node, 40-dim gather ------------------------
__global__ __launch_bounds__(256) void agg2_kernel(int n) {
    int gt = blockIdx.x * blockDim.x + threadIdx.x;
    int w = gt >> 5;
    int lane = gt & 31;
    if (w >= n || lane >= 20) return;
    const float2* y2 = (const float2*)g_y1;
    float2* o2 = (float2*)g_agg;
    float2 acc = y2[(size_t)w * 20 + lane];
    int s0 = g_offs[w], s1 = g_offs[w + 1];
    for (int j = s0; j < s1; j++) {
        int s = g_csr[j];
        float2 v = __ldg(&y2[(size_t)s * 20 + lane]);
        acc.x += v.x; acc.y += v.y;
    }
    o2[(size_t)w * 20 + lane] = acc;
}

// ---------------- final: out = softmax(relu(aggy + b2a) @ W2b + b2b) --------
#define G2B_ROWS 256
#define G2B_SMEM_FLOATS (G2B_ROWS * 41 + 40 * 40 + 40 + 40)
__global__ __launch_bounds__(256) void gemm2b_kernel(
    const float* __restrict__ b2a, const float* __restrict__ W2b,
    const float* __restrict__ b2b, float* __restrict__ out, int n) {
    extern __shared__ float sm[];
    float* As = sm;
    float* Wb = sm + G2B_ROWS * 41;
    float* ba = Wb + 40 * 40;
    float* bb = ba + 40;

    int tid = threadIdx.x;
    int row0 = blockIdx.x * G2B_ROWS;
    const float* A = g_agg;

    for (int i = tid; i < G2B_ROWS * 40; i += 256) {
        int r = i / 40, c = i - r * 40;
        int row = row0 + r;
        As[r * 41 + c] = (row < n) ? A[(size_t)row * 40 + c] : 0.f;
    }
    for (int i = tid; i < 1600; i += 256) Wb[i] = W2b[i];
    if (tid < 40) { ba[tid] = b2a[tid]; bb[tid] = b2b[tid]; }
    __syncthreads();

    float h[40];
    const float* arow = &As[tid * 41];
#pragma unroll
    for (int c = 0; c < 40; c++) h[c] = fmaxf(arow[c] + ba[c], 0.f);

    float o[40];
#pragma unroll
    for (int c = 0; c < 40; c++) o[c] = bb[c];
#pragma unroll 4
    for (int k = 0; k < 40; k++) {
        float a = h[k];
        const float4* w = (const float4*)&Wb[k * 40];
#pragma unroll
        for (int q = 0; q < 10; q++) {
            float4 wv = w[q];
            o[q * 4 + 0] = fmaf(a, wv.x, o[q * 4 + 0]);
            o[q * 4 + 1] = fmaf(a, wv.y, o[q * 4 + 1]);
            o[q * 4 + 2] = fmaf(a, wv.z, o[q * 4 + 2]);
            o[q * 4 + 3] = fmaf(a, wv.w, o[q * 4 + 3]);
        }
    }
    float mx = o[0];
#pragma unroll
    for (int c = 1; c < 40; c++) mx = fmaxf(mx, o[c]);
    float s = 0.f;
#pragma unroll
    for (int c = 0; c < 40; c++) { float e = __expf(o[c] - mx); o[c] = e; s += e; }
    float inv = 1.0f / s;
#pragma unroll
    for (int c = 0; c < 40; c++) As[tid * 41 + c] = o[c] * inv;
    __syncthreads();
    for (int i = tid; i < G2B_ROWS * 40; i += 256) {
        int r = i / 40, c = i - r * 40;
        int row = row0 + r;
        if (row < n) out[(size_t)row * 40 + c] = As[r * 41 + c];
    }
}

// ---------------- launcher --------------------------------------------------
extern "C" void kernel_launch(void* const* d_in, const int* in_sizes, int n_in,
                              void* d_out, int out_size) {
    int i_nodes = 0, i_edges = -1;
    for (int i = 1; i < n_in; i++)
        if (in_sizes[i] > in_sizes[i_nodes]) i_nodes = i;
    for (int i = 0; i < n_in; i++) {
        if (i == i_nodes) continue;
        if (i_edges < 0 || in_sizes[i] > in_sizes[i_edges]) i_edges = i;
    }

    const float* x0  = (const float*)d_in[i_nodes];
    const int2*  ei  = (const int2*)d_in[i_edges];
    int n = in_sizes[i_nodes] / DIM;
    int m = in_sizes[i_edges] / 2;

    const float *W1a = 0, *W1b = 0, *b1a = 0, *b1b = 0;
    const float *W2a = 0, *W2b = 0, *b2a = 0, *b2b = 0;
    for (int i = 0; i < n_in; i++) {
        if (i == i_nodes || i == i_edges) continue;
        int s = in_sizes[i];
        const float* p = (const float*)d_in[i];
        if (s == DIM * DIM)        { if (!W1a) W1a = p; else W1b = p; }
        else if (s == DIM)         { if (!b1a) b1a = p; else b1b = p; }
        else if (s == DIM * NCLS)  W2a = p;
        else if (s == NCLS * NCLS) W2b = p;
        else if (s == NCLS)        { if (!b2a) b2a = p; else b2b = p; }
    }
    float* out = (float*)d_out;

    const int y1_smem  = Y1_SMEM_FLOATS * (int)sizeof(float);
    const int g2b_smem = G2B_SMEM_FLOATS * (int)sizeof(float);
    cudaFuncSetAttribute(gemm1_kernel, cudaFuncAttributeMaxDynamicSharedMemorySize, G1_SMEM_BYTES);
    cudaFuncSetAttribute(y1_kernel, cudaFuncAttributeMaxDynamicSharedMemorySize, y1_smem);
    cudaFuncSetAttribute(gemm2b_kernel, cudaFuncAttributeMaxDynamicSharedMemorySize, g2b_smem);

    int nb = (n + SCB - 1) / SCB;  // 25 for n=100k

    // CSR build — multi-block coalesced scan
    zero_deg_kernel<<<(n + 255) / 256, 256>>>(n);
    hist_kernel<<<(m + 255) / 256, 256>>>(ei, m);
    scan_partial_kernel<<<nb, 256>>>(n);
    scan_tops_kernel<<<1, 32>>>(nb, n);
    scan_final_kernel<<<nb, 256>>>(n);
    fill_kernel<<<(m + 255) / 256, 256>>>(ei, m);

    // layer 1
    agg_kernel<<<((size_t)n * 32 + 255) / 256, 256>>>((const float4*)x0, n);
    gemm1_kernel<<<(n + 63) / 64, 256, G1_SMEM_BYTES>>>(W1a, b1a, W1b, b1b, n);

    // layer 2 (project -> aggregate -> tiny GEMM + softmax)
    y1_kernel<<<(n + 127) / 128, 128, y1_smem>>>(W2a, n);
    agg2_kernel<<<((size_t)n * 32 + 255) / 256, 256>>>(n);
    gemm2b_kernel<<<(n + G2B_ROWS - 1) / G2B_ROWS, 256, g2b_smem>>>(b2a, W2b, b2b, out, n);
}

// round 12
// speedup vs baseline: 2.3742x; 1.1013x over previous
#include <cuda_runtime.h>
#include <cuda_bf16.h>
#include <math.h>

#define N_NODES_MAX 100000
#define N_EDGES_MAX 1600000
#define DIM 128
#define NCLS 40
#define SCB 4096  // elements per scan block

// ---------------- bf16 split helpers ----------------------------------------
__device__ __forceinline__ unsigned pack_bf2(__nv_bfloat16 a, __nv_bfloat16 b) {
    __nv_bfloat162 t;
    t.x = a; t.y = b;
    return *reinterpret_cast<unsigned*>(&t);
}
__device__ __forceinline__ void split_bf(float f, __nv_bfloat16& hi, __nv_bfloat16& lo) {
    hi = __float2bfloat16_rn(f);
    lo = __float2bfloat16_rn(f - __bfloat162float(hi));
}
__device__ __forceinline__ void mma_bf16(float* c, unsigned a0, unsigned a1,
                                         unsigned a2, unsigned a3,
                                         unsigned b0, unsigned b1) {
    asm volatile(
        "mma.sync.aligned.m16n8k16.row.col.f32.bf16.bf16.f32 "
        "{%0,%1,%2,%3}, {%4,%5,%6,%7}, {%8,%9}, {%0,%1,%2,%3};"
        : "+f"(c[0]), "+f"(c[1]), "+f"(c[2]), "+f"(c[3])
        : "r"(a0), "r"(a1), "r"(a2), "r"(a3), "r"(b0), "r"(b1));
}

// ---------------- scratch (static device allocations; no cudaMalloc) -------
__device__ int g_deg[N_NODES_MAX];
__device__ int g_offs[N_NODES_MAX + 1];
__device__ int g_cur[N_NODES_MAX];
__device__ int g_csr[N_EDGES_MAX];
__device__ int g_bsum[64];
__device__ int g_boff[64];
__device__ __align__(16) float g_agg[(size_t)N_NODES_MAX * DIM];
__device__ __align__(16) float g_y1[(size_t)N_NODES_MAX * NCLS];

// ---------------- CSR build -------------------------------------------------
__global__ void hist_kernel(const int2* __restrict__ e, int m) {
    int i = blockIdx.x * blockDim.x + threadIdx.x;
    if (i < m) atomicAdd(&g_deg[e[i].y], 1);
}

__global__ __launch_bounds__(256) void scan_partial_kernel(int n) {
    __shared__ int s[SCB];
    __shared__ int ws[8];
    int base = blockIdx.x * SCB;
    int tid = threadIdx.x;
    for (int j = tid; j < SCB; j += 256)
        s[j] = (base + j < n) ? g_deg[base + j] : 0;
    __syncthreads();
    int mysum = 0;
#pragma unroll
    for (int j = 0; j < 16; j++) mysum += s[tid * 16 + j];
    int lane = tid & 31, wid = tid >> 5;
    int v = mysum;
#pragma unroll
    for (int o = 16; o > 0; o >>= 1) v += __shfl_down_sync(0xffffffffu, v, o);
    if (lane == 0) ws[wid] = v;
    __syncthreads();
    if (tid == 0) {
        int t = 0;
#pragma unroll
        for (int i = 0; i < 8; i++) t += ws[i];
        g_bsum[blockIdx.x] = t;
    }
}

__global__ void scan_tops_kernel(int nb, int n) {
    int t = threadIdx.x;  // 32 threads
    int x = (t < nb) ? g_bsum[t] : 0;
    int v = x;
#pragma unroll
    for (int o = 1; o < 32; o <<= 1) {
        int u = __shfl_up_sync(0xffffffffu, v, o);
        if (t >= o) v += u;
    }
    if (t < nb) g_boff[t] = v - x;
    if (t == 31) g_offs[n] = v;
}

__global__ __launch_bounds__(256) void scan_final_kernel(int n) {
    __shared__ int s[SCB];
    __shared__ int ws[8];
    int base = blockIdx.x * SCB;
    int tid = threadIdx.x;
    for (int j = tid; j < SCB; j += 256)
        s[j] = (base + j < n) ? g_deg[base + j] : 0;
    __syncthreads();
    int mysum = 0;
#pragma unroll
    for (int j = 0; j < 16; j++) mysum += s[tid * 16 + j];
    int lane = tid & 31, wid = tid >> 5;
    int v = mysum;
#pragma unroll
    for (int o = 1; o < 32; o <<= 1) {
        int u = __shfl_up_sync(0xffffffffu, v, o);
        if (lane >= o) v += u;
    }
    if (lane == 31) ws[wid] = v;
    __syncthreads();
    if (wid == 0 && lane < 8) {
        int w = ws[lane];
#pragma unroll
        for (int o = 1; o < 8; o <<= 1) {
            int u = __shfl_up_sync(0xffu, w, o);
            if (lane >= o) w += u;
        }
        ws[lane] = w;
    }
    __syncthreads();
    int run = (v - mysum) + ((wid > 0) ? ws[wid - 1] : 0) + g_boff[blockIdx.x];
#pragma unroll
    for (int j = 0; j < 16; j++) {
        int idx = tid * 16 + j;
        int t = s[idx];
        s[idx] = run;
        run += t;
    }
    __syncthreads();
    for (int j = tid; j < SCB; j += 256) {
        int gi = base + j;
        if (gi < n) { g_offs[gi] = s[j]; g_cur[gi] = s[j]; }
    }
}

__global__ void fill_kernel(const int2* __restrict__ e, int m) {
    int i = blockIdx.x * blockDim.x + threadIdx.x;
    if (i < m) {
        int2 ed = e[i];
        int p = atomicAdd(&g_cur[ed.y], 1);
        g_csr[p] = ed.x;
    }
}

// ---------------- agg1: warp per node, 128-dim gather -----------------------
__global__ __launch_bounds__(256) void agg_kernel(const float4* __restrict__ x4, int n) {
    int gt = blockIdx.x * blockDim.x + threadIdx.x;
    int w = gt >> 5;
    int lane = gt & 31;
    if (w >= n) return;
    float4* o4 = (float4*)g_agg;
    float4 acc = x4[(size_t)w * 32 + lane];
    int s0 = g_offs[w], s1 = g_offs[w + 1];
    for (int j = s0; j < s1; j++) {
        int s = g_csr[j];
        float4 v = __ldg(&x4[(size_t)s * 32 + lane]);
        acc.x += v.x; acc.y += v.y; acc.z += v.z; acc.w += v.w;
    }
    o4[(size_t)w * 32 + lane] = acc;
}

// ---------------- layer 1 + y1 projection via split-bf16 MMA ----------------
// phase1: T = relu(agg@W1a + b1a)
// phase2: X = relu(T@W1b + b1b)   (kept in smem only)
// phase3: y1 = X@W2a              (written to g_y1; x1 never materialized)
#define SAW 68
#define OFF_A2H 0
#define OFF_A2L (OFF_A2H + 64 * SAW)
#define OFF_WTH (OFF_A2L + 64 * SAW)
#define OFF_WTL (OFF_WTH + 128 * SAW)
#define OFF_BSA (OFF_WTL + 128 * SAW)
#define OFF_BSB (OFF_BSA + 128)
#define G1_SMEM_WORDS (OFF_BSB + 128)
#define G1_SMEM_BYTES (G1_SMEM_WORDS * 4)

__device__ __forceinline__ void g1_convert_W(unsigned* WTH, unsigned* WTL,
                                             const float* __restrict__ W, int tid) {
    // W row-major [k][128] -> WT n-major bf16x2 pairs [n][kpair]
    for (int i = tid; i < 64 * 128; i += 256) {
        int kp = i >> 7;
        int nn = i & 127;
        float f0 = W[(2 * kp) * 128 + nn];
        float f1 = W[(2 * kp + 1) * 128 + nn];
        __nv_bfloat16 h0, l0, h1, l1;
        split_bf(f0, h0, l0);
        split_bf(f1, h1, l1);
        WTH[nn * SAW + kp] = pack_bf2(h0, h1);
        WTL[nn * SAW + kp] = pack_bf2(l0, l1);
    }
}

// W2a row-major [k][40] -> WT n-major pairs for n in 0..39
__device__ __forceinline__ void g1_convert_W2a(unsigned* WTH, unsigned* WTL,
                                               const float* __restrict__ W, int tid) {
    for (int i = tid; i < 64 * 40; i += 256) {
        int kp = i / 40;
        int nn = i - kp * 40;
        float f0 = W[(2 * kp) * 40 + nn];
        float f1 = W[(2 * kp + 1) * 40 + nn];
        __nv_bfloat16 h0, l0, h1, l1;
        split_bf(f0, h0, l0);
        split_bf(f1, h1, l1);
        WTH[nn * SAW + kp] = pack_bf2(h0, h1);
        WTL[nn * SAW + kp] = pack_bf2(l0, l1);
    }
}

__global__ __launch_bounds__(256) void gemm1_kernel(
    const float* __restrict__ W1a, const float* __restrict__ b1a,
    const float* __restrict__ W1b, const float* __restrict__ b1b,
    const float* __restrict__ W2a, int n) {
    extern __shared__ unsigned su[];
    unsigned* A2H = su + OFF_A2H;
    unsigned* A2L = su + OFF_A2L;
    unsigned* WTH = su + OFF_WTH;
    unsigned* WTL = su + OFF_WTL;
    float* bsA = (float*)(su + OFF_BSA);
    float* bsB = (float*)(su + OFF_BSB);

    int tid = threadIdx.x;
    int lane = tid & 31, wid = tid >> 5;
    int r0 = (wid >> 1) << 4;   // warp row base (0,16,32,48)
    int n0 = (wid & 1) << 6;    // warp col base (0,64)
    int row0 = blockIdx.x * 64;

    // stage A tile (convert f32 -> bf16 hi/lo pairs)
    for (int i = tid; i < 64 * 32; i += 256) {
        int r = i >> 5, c = i & 31;
        float4 v = (row0 + r < n) ? ((const float4*)g_agg)[(size_t)(row0 + r) * 32 + c]
                                  : make_float4(0.f, 0.f, 0.f, 0.f);
        __nv_bfloat16 hx, lx, hy, ly, hz, lz, hw, lw;
        split_bf(v.x, hx, lx); split_bf(v.y, hy, ly);
        split_bf(v.z, hz, lz); split_bf(v.w, hw, lw);
        A2H[r * SAW + 2 * c + 0] = pack_bf2(hx, hy);
        A2H[r * SAW + 2 * c + 1] = pack_bf2(hz, hw);
        A2L[r * SAW + 2 * c + 0] = pack_bf2(lx, ly);
        A2L[r * SAW + 2 * c + 1] = pack_bf2(lz, lw);
    }
    g1_convert_W(WTH, WTL, W1a, tid);
    if (tid < 128) { bsA[tid] = b1a[tid]; bsB[tid] = b1b[tid]; }
    __syncthreads();

    float acc[8][4];
#pragma unroll
    for (int t = 0; t < 8; t++)
#pragma unroll
        for (int q = 0; q < 4; q++) acc[t][q] = 0.f;

    int arow = (r0 + (lane >> 2)) * SAW + (lane & 3);
    // ---------------- phase 1 mma ----------------
    for (int kk = 0; kk < 8; kk++) {
        int aw = arow + kk * 8;
        unsigned ah0 = A2H[aw], ah1 = A2H[aw + 8 * SAW];
        unsigned ah2 = A2H[aw + 4], ah3 = A2H[aw + 8 * SAW + 4];
        unsigned al0 = A2L[aw], al1 = A2L[aw + 8 * SAW];
        unsigned al2 = A2L[aw + 4], al3 = A2L[aw + 8 * SAW + 4];
#pragma unroll
        for (int t = 0; t < 8; t++) {
            int bw = (n0 + t * 8 + (lane >> 2)) * SAW + kk * 8 + (lane & 3);
            unsigned bh0 = WTH[bw], bh1 = WTH[bw + 4];
            unsigned bl0 = WTL[bw], bl1 = WTL[bw + 4];
            mma_bf16(acc[t], ah0, ah1, ah2, ah3, bh0, bh1);
            mma_bf16(acc[t], ah0, ah1, ah2, ah3, bl0, bl1);
            mma_bf16(acc[t], al0, al1, al2, al3, bh0, bh1);
        }
    }
    __syncthreads();

    // epilogue 1: T = relu(acc + b1a) -> A2; load W1b
    {
        int row = r0 + (lane >> 2);
#pragma unroll
        for (int t = 0; t < 8; t++) {
            int col = n0 + t * 8 + (lane & 3) * 2;
            int pair = col >> 1;
            float h00 = fmaxf(acc[t][0] + bsA[col], 0.f);
            float h01 = fmaxf(acc[t][1] + bsA[col + 1], 0.f);
            float h10 = fmaxf(acc[t][2] + bsA[col], 0.f);
            float h11 = fmaxf(acc[t][3] + bsA[col + 1], 0.f);
            __nv_bfloat16 h, l, h2, l2;
            split_bf(h00, h, l); split_bf(h01, h2, l2);
            A2H[row * SAW + pair] = pack_bf2(h, h2);
            A2L[row * SAW + pair] = pack_bf2(l, l2);
            split_bf(h10, h, l); split_bf(h11, h2, l2);
            A2H[(row + 8) * SAW + pair] = pack_bf2(h, h2);
            A2L[(row + 8) * SAW + pair] = pack_bf2(l, l2);
            acc[t][0] = acc[t][1] = acc[t][2] = acc[t][3] = 0.f;
        }
    }
    g1_convert_W(WTH, WTL, W1b, tid);
    __syncthreads();

    // ---------------- phase 2 mma ----------------
    for (int kk = 0; kk < 8; kk++) {
        int aw = arow + kk * 8;
        unsigned ah0 = A2H[aw], ah1 = A2H[aw + 8 * SAW];
        unsigned ah2 = A2H[aw + 4], ah3 = A2H[aw + 8 * SAW + 4];
        unsigned al0 = A2L[aw], al1 = A2L[aw + 8 * SAW];
        unsigned al2 = A2L[aw + 4], al3 = A2L[aw + 8 * SAW + 4];
#pragma unroll
        for (int t = 0; t < 8; t++) {
            int bw = (n0 + t * 8 + (lane >> 2)) * SAW + kk * 8 + (lane & 3);
            unsigned bh0 = WTH[bw], bh1 = WTH[bw + 4];
            unsigned bl0 = WTL[bw], bl1 = WTL[bw + 4];
            mma_bf16(acc[t], ah0, ah1, ah2, ah3, bh0, bh1);
            mma_bf16(acc[t], ah0, ah1, ah2, ah3, bl0, bl1);
            mma_bf16(acc[t], al0, al1, al2, al3, bh0, bh1);
        }
    }
    __syncthreads();  // phase-2 reads of A2/WT complete before overwrite

    // epilogue 2: X = relu(acc + b1b) -> A2 (hi/lo); convert W2a
    {
        int row = r0 + (lane >> 2);
#pragma unroll
        for (int t = 0; t < 8; t++) {
            int col = n0 + t * 8 + (lane & 3) * 2;
            int pair = col >> 1;
            float h00 = fmaxf(acc[t][0] + bsB[col], 0.f);
            float h01 = fmaxf(acc[t][1] + bsB[col + 1], 0.f);
            float h10 = fmaxf(acc[t][2] + bsB[col], 0.f);
            float h11 = fmaxf(acc[t][3] + bsB[col + 1], 0.f);
            __nv_bfloat16 h, l, h2, l2;
            split_bf(h00, h, l); split_bf(h01, h2, l2);
            A2H[row * SAW + pair] = pack_bf2(h, h2);
            A2L[row * SAW + pair] = pack_bf2(l, l2);
            split_bf(h10, h, l); split_bf(h11, h2, l2);
            A2H[(row + 8) * SAW + pair] = pack_bf2(h, h2);
            A2L[(row + 8) * SAW + pair] = pack_bf2(l, l2);
        }
    }
    g1_convert_W2a(WTH, WTL, W2a, tid);
    __syncthreads();

    // ---------------- phase 3 mma: y1 = X @ W2a (warps with wid&1==0) -------
    if ((wid & 1) == 0) {
        float accy[5][4];
#pragma unroll
        for (int t = 0; t < 5; t++)
#pragma unroll
            for (int q = 0; q < 4; q++) accy[t][q] = 0.f;

        for (int kk = 0; kk < 8; kk++) {
            int aw = arow + kk * 8;
            unsigned ah0 = A2H[aw], ah1 = A2H[aw + 8 * SAW];
            unsigned ah2 = A2H[aw + 4], ah3 = A2H[aw + 8 * SAW + 4];
            unsigned al0 = A2L[aw], al1 = A2L[aw + 8 * SAW];
            unsigned al2 = A2L[aw + 4], al3 = A2L[aw + 8 * SAW + 4];
#pragma unroll
            for (int t = 0; t < 5; t++) {
                int bw = (t * 8 + (lane >> 2)) * SAW + kk * 8 + (lane & 3);
                unsigned bh0 = WTH[bw], bh1 = WTH[bw + 4];
                unsigned bl0 = WTL[bw], bl1 = WTL[bw + 4];
                mma_bf16(accy[t], ah0, ah1, ah2, ah3, bh0, bh1);
                mma_bf16(accy[t], ah0, ah1, ah2, ah3, bl0, bl1);
                mma_bf16(accy[t], al0, al1, al2, al3, bh0, bh1);
            }
        }
        int row = row0 + r0 + (lane >> 2);
#pragma unroll
        for (int t = 0; t < 5; t++) {
            int col = t * 8 + (lane & 3) * 2;
            if (row < n) {
                float2 o; o.x = accy[t][0]; o.y = accy[t][1];
                *(float2*)&g_y1[(size_t)row * 40 + col] = o;
            }
            if (row + 8 < n) {
                float2 o; o.x = accy[t][2]; o.y = accy[t][3];
                *(float2*)&g_y1[(size_t)(row + 8) * 40 + col] = o;
            }
        }
    }
}

// ---------------- final: out = softmax(relu(agg(y1) + b2a) @ W2b + b2b) -----
// agg2 fused into staging: warp gathers 32 nodes' 40-float rows via CSR.
#define G2B_ROWS 256
#define G2B_SMEM_FLOATS (G2B_ROWS * 41 + 40 * 40 + 40 + 40)
__global__ __launch_bounds__(256) void gemm2b_kernel(
    const float* __restrict__ b2a, const float* __restrict__ W2b,
    const float* __restrict__ b2b, float* __restrict__ out, int n) {
    extern __shared__ float sm[];
    float* As = sm;
    float* Wb = sm + G2B_ROWS * 41;
    float* ba = Wb + 40 * 40;
    float* bb = ba + 40;

    int tid = threadIdx.x;
    int lane = tid & 31, wid = tid >> 5;
    int row0 = blockIdx.x * G2B_ROWS;
    const float2* y2 = (const float2*)g_y1;

    // fused aggregation staging: node = row0 + wid*32 + i
    for (int i = 0; i < 32; i++) {
        int r = wid * 32 + i;
        int row = row0 + r;
        float2 acc = make_float2(0.f, 0.f);
        if (row < n) {
            int s0 = g_offs[row], s1 = g_offs[row + 1];
            if (lane < 20) {
                acc = y2[(size_t)row * 20 + lane];  // self term
                for (int j = s0; j < s1; j++) {
                    int s = g_csr[j];
                    float2 v = __ldg(&y2[(size_t)s * 20 + lane]);
                    acc.x += v.x; acc.y += v.y;
                }
            }
        }
        if (lane < 20) {
            As[r * 41 + 2 * lane + 0] = acc.x;
            As[r * 41 + 2 * lane + 1] = acc.y;
        }
    }
    for (int i = tid; i < 1600; i += 256) Wb[i] = W2b[i];
    if (tid < 40) { ba[tid] = b2a[tid]; bb[tid] = b2b[tid]; }
    __syncthreads();

    float h[40];
    const float* arow = &As[tid * 41];
#pragma unroll
    for (int c = 0; c < 40; c++) h[c] = fmaxf(arow[c] + ba[c], 0.f);

    float o[40];
#pragma unroll
    for (int c = 0; c < 40; c++) o[c] = bb[c];
#pragma unroll 4
    for (int k = 0; k < 40; k++) {
        float a = h[k];
        const float4* w = (const float4*)&Wb[k * 40];
#pragma unroll
        for (int q = 0; q < 10; q++) {
            float4 wv = w[q];
            o[q * 4 + 0] = fmaf(a, wv.x, o[q * 4 + 0]);
            o[q * 4 + 1] = fmaf(a, wv.y, o[q * 4 + 1]);
            o[q * 4 + 2] = fmaf(a, wv.z, o[q * 4 + 2]);
            o[q * 4 + 3] = fmaf(a, wv.w, o[q * 4 + 3]);
        }
    }
    float mx = o[0];
#pragma unroll
    for (int c = 1; c < 40; c++) mx = fmaxf(mx, o[c]);
    float s = 0.f;
#pragma unroll
    for (int c = 0; c < 40; c++) { float e = __expf(o[c] - mx); o[c] = e; s += e; }
    float inv = 1.0f / s;
#pragma unroll
    for (int c = 0; c < 40; c++) As[tid * 41 + c] = o[c] * inv;
    __syncthreads();
    for (int i = tid; i < G2B_ROWS * 40; i += 256) {
        int r = i / 40, c = i - r * 40;
        int row = row0 + r;
        if (row < n) out[(size_t)row * 40 + c] = As[r * 41 + c];
    }
}

// ---------------- launcher --------------------------------------------------
extern "C" void kernel_launch(void* const* d_in, const int* in_sizes, int n_in,
                              void* d_out, int out_size) {
    int i_nodes = 0, i_edges = -1;
    for (int i = 1; i < n_in; i++)
        if (in_sizes[i] > in_sizes[i_nodes]) i_nodes = i;
    for (int i = 0; i < n_in; i++) {
        if (i == i_nodes) continue;
        if (i_edges < 0 || in_sizes[i] > in_sizes[i_edges]) i_edges = i;
    }

    const float* x0  = (const float*)d_in[i_nodes];
    const int2*  ei  = (const int2*)d_in[i_edges];
    int n = in_sizes[i_nodes] / DIM;
    int m = in_sizes[i_edges] / 2;

    const float *W1a = 0, *W1b = 0, *b1a = 0, *b1b = 0;
    const float *W2a = 0, *W2b = 0, *b2a = 0, *b2b = 0;
    for (int i = 0; i < n_in; i++) {
        if (i == i_nodes || i == i_edges) continue;
        int s = in_sizes[i];
        const float* p = (const float*)d_in[i];
        if (s == DIM * DIM)        { if (!W1a) W1a = p; else W1b = p; }
        else if (s == DIM)         { if (!b1a) b1a = p; else b1b = p; }
        else if (s == DIM * NCLS)  W2a = p;
        else if (s == NCLS * NCLS) W2b = p;
        else if (s == NCLS)        { if (!b2a) b2a = p; else b2b = p; }
    }
    float* out = (float*)d_out;

    const int g2b_smem = G2B_SMEM_FLOATS * (int)sizeof(float);
    cudaFuncSetAttribute(gemm1_kernel, cudaFuncAttributeMaxDynamicSharedMemorySize, G1_SMEM_BYTES);
    cudaFuncSetAttribute(gemm2b_kernel, cudaFuncAttributeMaxDynamicSharedMemorySize, g2b_smem);

    void* deg_ptr;
    cudaGetSymbolAddress(&deg_ptr, g_deg);

    int nb = (n + SCB - 1) / SCB;  // 25 for n=100k

    // CSR build
    cudaMemsetAsync(deg_ptr, 0, (size_t)n * sizeof(int));
    hist_kernel<<<(m + 255) / 256, 256>>>(ei, m);
    scan_partial_kernel<<<nb, 256>>>(n);
    scan_tops_kernel<<<1, 32>>>(nb, n);
    scan_final_kernel<<<nb, 256>>>(n);
    fill_kernel<<<(m + 255) / 256, 256>>>(ei, m);

    // layer 1 + y1 projection (x1 never materialized)
    agg_kernel<<<((size_t)n * 32 + 255) / 256, 256>>>((const float4*)x0, n);
    gemm1_kernel<<<(n + 63) / 64, 256, G1_SMEM_BYTES>>>(W1a, b1a, W1b, b1b, W2a, n);

    // layer 2: fused aggregate + tiny GEMM + softmax
    gemm2b_kernel<<<(n + G2B_ROWS - 1) / G2B_ROWS, 256, g2b_smem>>>(b2a, W2b, b2b, out, n);
}

// round 15
// speedup vs baseline: 2.4165x; 1.0178x over previous
#include <cuda_runtime.h>
#include <cuda_bf16.h>
#include <math.h>

#define N_NODES_MAX 100000
#define N_EDGES_MAX 1600000
#define DIM 128
#define NCLS 40
#define SCB 4096  // elements per scan block

// ---------------- bf16 split helpers ----------------------------------------
__device__ __forceinline__ unsigned pack_bf2(__nv_bfloat16 a, __nv_bfloat16 b) {
    __nv_bfloat162 t;
    t.x = a; t.y = b;
    return *reinterpret_cast<unsigned*>(&t);
}
__device__ __forceinline__ void split_bf(float f, __nv_bfloat16& hi, __nv_bfloat16& lo) {
    hi = __float2bfloat16_rn(f);
    lo = __float2bfloat16_rn(f - __bfloat162float(hi));
}
__device__ __forceinline__ void mma_bf16(float* c, unsigned a0, unsigned a1,
                                         unsigned a2, unsigned a3,
                                         unsigned b0, unsigned b1) {
    asm volatile(
        "mma.sync.aligned.m16n8k16.row.col.f32.bf16.bf16.f32 "
        "{%0,%1,%2,%3}, {%4,%5,%6,%7}, {%8,%9}, {%0,%1,%2,%3};"
        : "+f"(c[0]), "+f"(c[1]), "+f"(c[2]), "+f"(c[3])
        : "r"(a0), "r"(a1), "r"(a2), "r"(a3), "r"(b0), "r"(b1));
}

// ---------------- scratch (static device allocations; no cudaMalloc) -------
__device__ int g_deg[N_NODES_MAX];
__device__ int g_offs[N_NODES_MAX + 1];
__device__ int g_cur[N_NODES_MAX];
__device__ int g_csr[N_EDGES_MAX];
__device__ int g_bsum[64];
__device__ __align__(16) float g_agg[(size_t)N_NODES_MAX * DIM];
__device__ __align__(16) float g_y1[(size_t)N_NODES_MAX * NCLS];
// pre-converted weights: packed bf16 (hi,lo) pairs in n-major [n][kpair] layout
__device__ unsigned g_wth1a[128 * 64];
__device__ unsigned g_wtl1a[128 * 64];
__device__ unsigned g_wth1b[128 * 64];
__device__ unsigned g_wtl1b[128 * 64];
__device__ unsigned g_wth2a[40 * 64];
__device__ unsigned g_wtl2a[40 * 64];

// ---------------- weight pre-conversion (runs once) -------------------------
__global__ void convert_weights_kernel(const float* __restrict__ W1a,
                                       const float* __restrict__ W1b,
                                       const float* __restrict__ W2a) {
    int i = blockIdx.x * blockDim.x + threadIdx.x;
    if (i < 8192) {
        int kp = i >> 7, nn = i & 127;  // coalesced source reads over nn
        __nv_bfloat16 h0, l0, h1, l1;
        float f0 = W1a[(2 * kp) * 128 + nn];
        float f1 = W1a[(2 * kp + 1) * 128 + nn];
        split_bf(f0, h0, l0); split_bf(f1, h1, l1);
        g_wth1a[nn * 64 + kp] = pack_bf2(h0, h1);
        g_wtl1a[nn * 64 + kp] = pack_bf2(l0, l1);
        f0 = W1b[(2 * kp) * 128 + nn];
        f1 = W1b[(2 * kp + 1) * 128 + nn];
        split_bf(f0, h0, l0); split_bf(f1, h1, l1);
        g_wth1b[nn * 64 + kp] = pack_bf2(h0, h1);
        g_wtl1b[nn * 64 + kp] = pack_bf2(l0, l1);
    }
    if (i < 2560) {
        int kp = i / 40, nn = i - kp * 40;
        __nv_bfloat16 h0, l0, h1, l1;
        float f0 = W2a[(2 * kp) * 40 + nn];
        float f1 = W2a[(2 * kp + 1) * 40 + nn];
        split_bf(f0, h0, l0); split_bf(f1, h1, l1);
        g_wth2a[nn * 64 + kp] = pack_bf2(h0, h1);
        g_wtl2a[nn * 64 + kp] = pack_bf2(l0, l1);
    }
}

// ---------------- CSR build -------------------------------------------------
__global__ void hist_kernel(const int2* __restrict__ e, int m) {
    int i = blockIdx.x * blockDim.x + threadIdx.x;
    if (i < m) atomicAdd(&g_deg[e[i].y], 1);
}

__global__ __launch_bounds__(256) void scan_partial_kernel(int n) {
    __shared__ int s[SCB];
    __shared__ int ws[8];
    int base = blockIdx.x * SCB;
    int tid = threadIdx.x;
    for (int j = tid; j < SCB; j += 256)
        s[j] = (base + j < n) ? g_deg[base + j] : 0;
    __syncthreads();
    int mysum = 0;
#pragma unroll
    for (int j = 0; j < 16; j++) mysum += s[tid * 16 + j];
    int lane = tid & 31, wid = tid >> 5;
    int v = mysum;
#pragma unroll
    for (int o = 16; o > 0; o >>= 1) v += __shfl_down_sync(0xffffffffu, v, o);
    if (lane == 0) ws[wid] = v;
    __syncthreads();
    if (tid == 0) {
        int t = 0;
#pragma unroll
        for (int i = 0; i < 8; i++) t += ws[i];
        g_bsum[blockIdx.x] = t;
    }
}

// per-block scan; block sums prefixed inline (scan_tops merged away)
__global__ __launch_bounds__(256) void scan_final_kernel(int n, int nb) {
    __shared__ int s[SCB];
    __shared__ int ws[8];
    __shared__ int boff_s;
    int base = blockIdx.x * SCB;
    int tid = threadIdx.x;
    if (tid == 0) {
        int acc = 0;
        for (int b = 0; b < nb; b++) {
            if (b == blockIdx.x) boff_s = acc;
            acc += g_bsum[b];
        }
        if (blockIdx.x == nb - 1) g_offs[n] = acc;
    }
    for (int j = tid; j < SCB; j += 256)
        s[j] = (base + j < n) ? g_deg[base + j] : 0;
    __syncthreads();
    int mysum = 0;
#pragma unroll
    for (int j = 0; j < 16; j++) mysum += s[tid * 16 + j];
    int lane = tid & 31, wid = tid >> 5;
    int v = mysum;
#pragma unroll
    for (int o = 1; o < 32; o <<= 1) {
        int u = __shfl_up_sync(0xffffffffu, v, o);
        if (lane >= o) v += u;
    }
    if (lane == 31) ws[wid] = v;
    __syncthreads();
    if (wid == 0 && lane < 8) {
        int w = ws[lane];
#pragma unroll
        for (int o = 1; o < 8; o <<= 1) {
            int u = __shfl_up_sync(0xffu, w, o);
            if (lane >= o) w += u;
        }
        ws[lane] = w;
    }
    __syncthreads();
    int run = (v - mysum) + ((wid > 0) ? ws[wid - 1] : 0) + boff_s;
#pragma unroll
    for (int j = 0; j < 16; j++) {
        int idx = tid * 16 + j;
        int t = s[idx];
        s[idx] = run;
        run += t;
    }
    __syncthreads();
    for (int j = tid; j < SCB; j += 256) {
        int gi = base + j;
        if (gi < n) { g_offs[gi] = s[j]; g_cur[gi] = s[j]; }
    }
}

__global__ void fill_kernel(const int2* __restrict__ e, int m) {
    int i = blockIdx.x * blockDim.x + threadIdx.x;
    if (i < m) {
        int2 ed = e[i];
        int p = atomicAdd(&g_cur[ed.y], 1);
        g_csr[p] = ed.x;
    }
}

// ---------------- agg1: warp per node, 128-dim gather -----------------------
__global__ __launch_bounds__(256) void agg_kernel(const float4* __restrict__ x4, int n) {
    int gt = blockIdx.x * blockDim.x + threadIdx.x;
    int w = gt >> 5;
    int lane = gt & 31;
    if (w >= n) return;
    float4* o4 = (float4*)g_agg;
    float4 acc = x4[(size_t)w * 32 + lane];
    int s0 = g_offs[w], s1 = g_offs[w + 1];
    for (int j = s0; j < s1; j++) {
        int s = g_csr[j];
        float4 v = __ldg(&x4[(size_t)s * 32 + lane]);
        acc.x += v.x; acc.y += v.y; acc.z += v.z; acc.w += v.w;
    }
    o4[(size_t)w * 32 + lane] = acc;
}

// ---------------- layer 1 + y1 projection via split-bf16 MMA ----------------
#define SAW 68
#define OFF_A2H 0
#define OFF_A2L (OFF_A2H + 64 * SAW)
#define OFF_WTH (OFF_A2L + 64 * SAW)
#define OFF_WTL (OFF_WTH + 128 * SAW)
#define OFF_BSA (OFF_WTL + 128 * SAW)
#define OFF_BSB (OFF_BSA + 128)
#define G1_SMEM_WORDS (OFF_BSB + 128)
#define G1_SMEM_BYTES (G1_SMEM_WORDS * 4)

__device__ __forceinline__ void g1_load_W128(unsigned* WTH, unsigned* WTL,
                                             const unsigned* __restrict__ GH,
                                             const unsigned* __restrict__ GL, int tid) {
    for (int i = tid; i < 8192; i += 256) {
        int kp = i & 63, nn = i >> 6;
        WTH[nn * SAW + kp] = GH[i];
        WTL[nn * SAW + kp] = GL[i];
    }
}

__global__ __launch_bounds__(256) void gemm1_kernel(
    const float* __restrict__ b1a, const float* __restrict__ b1b, int n) {
    extern __shared__ unsigned su[];
    unsigned* A2H = su + OFF_A2H;
    unsigned* A2L = su + OFF_A2L;
    unsigned* WTH = su + OFF_WTH;
    unsigned* WTL = su + OFF_WTL;
    float* bsA = (float*)(su + OFF_BSA);
    float* bsB = (float*)(su + OFF_BSB);

    int tid = threadIdx.x;
    int lane = tid & 31, wid = tid >> 5;
    int r0 = (wid >> 1) << 4;   // warp row base (0,16,32,48)
    int n0 = (wid & 1) << 6;    // warp col base (0,64)
    int row0 = blockIdx.x * 64;

    // stage A tile (convert f32 -> bf16 hi/lo pairs)
    for (int i = tid; i < 64 * 32; i += 256) {
        int r = i >> 5, c = i & 31;
        float4 v = (row0 + r < n) ? ((const float4*)g_agg)[(size_t)(row0 + r) * 32 + c]
                                  : make_float4(0.f, 0.f, 0.f, 0.f);
        __nv_bfloat16 hx, lx, hy, ly, hz, lz, hw, lw;
        split_bf(v.x, hx, lx); split_bf(v.y, hy, ly);
        split_bf(v.z, hz, lz); split_bf(v.w, hw, lw);
        A2H[r * SAW + 2 * c + 0] = pack_bf2(hx, hy);
        A2H[r * SAW + 2 * c + 1] = pack_bf2(hz, hw);
        A2L[r * SAW + 2 * c + 0] = pack_bf2(lx, ly);
        A2L[r * SAW + 2 * c + 1] = pack_bf2(lz, lw);
    }
    g1_load_W128(WTH, WTL, g_wth1a, g_wtl1a, tid);
    if (tid < 128) { bsA[tid] = b1a[tid]; bsB[tid] = b1b[tid]; }
    __syncthreads();

    float acc[8][4];
#pragma unroll
    for (int t = 0; t < 8; t++)
#pragma unroll
        for (int q = 0; q < 4; q++) acc[t][q] = 0.f;

    int arow = (r0 + (lane >> 2)) * SAW + (lane & 3);
    // ---------------- phase 1 mma ----------------
    for (int kk = 0; kk < 8; kk++) {
        int aw = arow + kk * 8;
        unsigned ah0 = A2H[aw], ah1 = A2H[aw + 8 * SAW];
        unsigned ah2 = A2H[aw + 4], ah3 = A2H[aw + 8 * SAW + 4];
        unsigned al0 = A2L[aw], al1 = A2L[aw + 8 * SAW];
        unsigned al2 = A2L[aw + 4], al3 = A2L[aw + 8 * SAW + 4];
#pragma unroll
        for (int t = 0; t < 8; t++) {
            int bw = (n0 + t * 8 + (lane >> 2)) * SAW + kk * 8 + (lane & 3);
            unsigned bh0 = WTH[bw], bh1 = WTH[bw + 4];
            unsigned bl0 = WTL[bw], bl1 = WTL[bw + 4];
            mma_bf16(acc[t], ah0, ah1, ah2, ah3, bh0, bh1);
            mma_bf16(acc[t], ah0, ah1, ah2, ah3, bl0, bl1);
            mma_bf16(acc[t], al0, al1, al2, al3, bh0, bh1);
        }
    }
    __syncthreads();

    // epilogue 1: T = relu(acc + b1a) -> A2; load W1b
    {
        int row = r0 + (lane >> 2);
#pragma unroll
        for (int t = 0; t < 8; t++) {
            int col = n0 + t * 8 + (lane & 3) * 2;
            int pair = col >> 1;
            float h00 = fmaxf(acc[t][0] + bsA[col], 0.f);
            float h01 = fmaxf(acc[t][1] + bsA[col + 1], 0.f);
            float h10 = fmaxf(acc[t][2] + bsA[col], 0.f);
            float h11 = fmaxf(acc[t][3] + bsA[col + 1], 0.f);
            __nv_bfloat16 h, l, h2, l2;
            split_bf(h00, h, l); split_bf(h01, h2, l2);
            A2H[row * SAW + pair] = pack_bf2(h, h2);
            A2L[row * SAW + pair] = pack_bf2(l, l2);
            split_bf(h10, h, l); split_bf(h11, h2, l2);
            A2H[(row + 8) * SAW + pair] = pack_bf2(h, h2);
            A2L[(row + 8) * SAW + pair] = pack_bf2(l, l2);
            acc[t][0] = acc[t][1] = acc[t][2] = acc[t][3] = 0.f;
        }
    }
    g1_load_W128(WTH, WTL, g_wth1b, g_wtl1b, tid);
    __syncthreads();

    // ---------------- phase 2 mma ----------------
    for (int kk = 0; kk < 8; kk++) {
        int aw = arow + kk * 8;
        unsigned ah0 = A2H[aw], ah1 = A2H[aw + 8 * SAW];
        unsigned ah2 = A2H[aw + 4], ah3 = A2H[aw + 8 * SAW + 4];
        unsigned al0 = A2L[aw], al1 = A2L[aw + 8 * SAW];
        unsigned al2 = A2L[aw + 4], al3 = A2L[aw + 8 * SAW + 4];
#pragma unroll
        for (int t = 0; t < 8; t++) {
            int bw = (n0 + t * 8 + (lane >> 2)) * SAW + kk * 8 + (lane & 3);
            unsigned bh0 = WTH[bw], bh1 = WTH[bw + 4];
            unsigned bl0 = WTL[bw], bl1 = WTL[bw + 4];
            mma_bf16(acc[t], ah0, ah1, ah2, ah3, bh0, bh1);
            mma_bf16(acc[t], ah0, ah1, ah2, ah3, bl0, bl1);
            mma_bf16(acc[t], al0, al1, al2, al3, bh0, bh1);
        }
    }
    __syncthreads();  // phase-2 reads complete before overwrite

    // epilogue 2: X = relu(acc + b1b) -> A2 (hi/lo); load W2a
    {
        int row = r0 + (lane >> 2);
#pragma unroll
        for (int t = 0; t < 8; t++) {
            int col = n0 + t * 8 + (lane & 3) * 2;
            int pair = col >> 1;
            float h00 = fmaxf(acc[t][0] + bsB[col], 0.f);
            float h01 = fmaxf(acc[t][1] + bsB[col + 1], 0.f);
            float h10 = fmaxf(acc[t][2] + bsB[col], 0.f);
            float h11 = fmaxf(acc[t][3] + bsB[col + 1], 0.f);
            __nv_bfloat16 h, l, h2, l2;
            split_bf(h00, h, l); split_bf(h01, h2, l2);
            A2H[row * SAW + pair] = pack_bf2(h, h2);
            A2L[row * SAW + pair] = pack_bf2(l, l2);
            split_bf(h10, h, l); split_bf(h11, h2, l2);
            A2H[(row + 8) * SAW + pair] = pack_bf2(h, h2);
            A2L[(row + 8) * SAW + pair] = pack_bf2(l, l2);
        }
    }
    for (int i = tid; i < 2560; i += 256) {
        int kp = i & 63, nn = i >> 6;
        WTH[nn * SAW + kp] = g_wth2a[i];
        WTL[nn * SAW + kp] = g_wtl2a[i];
    }
    __syncthreads();

    // ---------------- phase 3 mma: y1 = X @ W2a (warps with wid&1==0) -------
    if ((wid & 1) == 0) {
        float accy[5][4];
#pragma unroll
        for (int t = 0; t < 5; t++)
#pragma unroll
            for (int q = 0; q < 4; q++) accy[t][q] = 0.f;

        for (int kk = 0; kk < 8; kk++) {
            int aw = arow + kk * 8;
            unsigned ah0 = A2H[aw], ah1 = A2H[aw + 8 * SAW];
            unsigned ah2 = A2H[aw + 4], ah3 = A2H[aw + 8 * SAW + 4];
            unsigned al0 = A2L[aw], al1 = A2L[aw + 8 * SAW];
            unsigned al2 = A2L[aw + 4], al3 = A2L[aw + 8 * SAW + 4];
#pragma unroll
            for (int t = 0; t < 5; t++) {
                int bw = (t * 8 + (lane >> 2)) * SAW + kk * 8 + (lane & 3);
                unsigned bh0 = WTH[bw], bh1 = WTH[bw + 4];
                unsigned bl0 = WTL[bw], bl1 = WTL[bw + 4];
                mma_bf16(accy[t], ah0, ah1, ah2, ah3, bh0, bh1);
                mma_bf16(accy[t], ah0, ah1, ah2, ah3, bl0, bl1);
                mma_bf16(accy[t], al0, al1, al2, al3, bh0, bh1);
            }
        }
        int row = row0 + r0 + (lane >> 2);
#pragma unroll
        for (int t = 0; t < 5; t++) {
            int col = t * 8 + (lane & 3) * 2;
            if (row < n) {
                float2 o; o.x = accy[t][0]; o.y = accy[t][1];
                *(float2*)&g_y1[(size_t)row * 40 + col] = o;
            }
            if (row + 8 < n) {
                float2 o; o.x = accy[t][2]; o.y = accy[t][3];
                *(float2*)&g_y1[(size_t)(row + 8) * 40 + col] = o;
            }
        }
    }
}

// ---------------- final: out = softmax(relu(agg(y1) + b2a) @ W2b + b2b) -----
#define G2B_ROWS 256
#define G2B_SMEM_FLOATS (G2B_ROWS * 41 + 40 * 40 + 40 + 40)
__global__ __launch_bounds__(256) void gemm2b_kernel(
    const float* __restrict__ b2a, const float* __restrict__ W2b,
    const float* __restrict__ b2b, float* __restrict__ out, int n) {
    extern __shared__ float sm[];
    float* As = sm;
    float* Wb = sm + G2B_ROWS * 41;
    float* ba = Wb + 40 * 40;
    float* bb = ba + 40;

    int tid = threadIdx.x;
    int lane = tid & 31, wid = tid >> 5;
    int row0 = blockIdx.x * G2B_ROWS;
    const float2* y2 = (const float2*)g_y1;

    for (int i = 0; i < 32; i++) {
        int r = wid * 32 + i;
        int row = row0 + r;
        float2 acc = make_float2(0.f, 0.f);
        if (row < n) {
            int s0 = g_offs[row], s1 = g_offs[row + 1];
            if (lane < 20) {
                acc = y2[(size_t)row * 20 + lane];
                for (int j = s0; j < s1; j++) {
                    int s = g_csr[j];
                    float2 v = __ldg(&y2[(size_t)s * 20 + lane]);
                    acc.x += v.x; acc.y += v.y;
                }
            }
        }
        if (lane < 20) {
            As[r * 41 + 2 * lane + 0] = acc.x;
            As[r * 41 + 2 * lane + 1] = acc.y;
        }
    }
    for (int i = tid; i < 1600; i += 256) Wb[i] = W2b[i];
    if (tid < 40) { ba[tid] = b2a[tid]; bb[tid] = b2b[tid]; }
    __syncthreads();

    float h[40];
    const float* arow = &As[tid * 41];
#pragma unroll
    for (int c = 0; c < 40; c++) h[c] = fmaxf(arow[c] + ba[c], 0.f);

    float o[40];
#pragma unroll
    for (int c = 0; c < 40; c++) o[c] = bb[c];
#pragma unroll 4
    for (int k = 0; k < 40; k++) {
        float a = h[k];
        const float4* w = (const float4*)&Wb[k * 40];
#pragma unroll
        for (int q = 0; q < 10; q++) {
            float4 wv = w[q];
            o[q * 4 + 0] = fmaf(a, wv.x, o[q * 4 + 0]);
            o[q * 4 + 1] = fmaf(a, wv.y, o[q * 4 + 1]);
            o[q * 4 + 2] = fmaf(a, wv.z, o[q * 4 + 2]);
            o[q * 4 + 3] = fmaf(a, wv.w, o[q * 4 + 3]);
        }
    }
    float mx = o[0];
#pragma unroll
    for (int c = 1; c < 40; c++) mx = fmaxf(mx, o[c]);
    float s = 0.f;
#pragma unroll
    for (int c = 0; c < 40; c++) { float e = __expf(o[c] - mx); o[c] = e; s += e; }
    float inv = 1.0f / s;
#pragma unroll
    for (int c = 0; c < 40; c++) As[tid * 41 + c] = o[c] * inv;
    __syncthreads();
    for (int i = tid; i < G2B_ROWS * 40; i += 256) {
        int r = i / 40, c = i - r * 40;
        int row = row0 + r;
        if (row < n) out[(size_t)row * 40 + c] = As[r * 41 + c];
    }
}

// ---------------- launcher --------------------------------------------------
extern "C" void kernel_launch(void* const* d_in, const int* in_sizes, int n_in,
                              void* d_out, int out_size) {
    int i_nodes = 0, i_edges = -1;
    for (int i = 1; i < n_in; i++)
        if (in_sizes[i] > in_sizes[i_nodes]) i_nodes = i;
    for (int i = 0; i < n_in; i++) {
        if (i == i_nodes) continue;
        if (i_edges < 0 || in_sizes[i] > in_sizes[i_edges]) i_edges = i;
    }

    const float* x0  = (const float*)d_in[i_nodes];
    const int2*  ei  = (const int2*)d_in[i_edges];
    int n = in_sizes[i_nodes] / DIM;
    int m = in_sizes[i_edges] / 2;

    const float *W1a = 0, *W1b = 0, *b1a = 0, *b1b = 0;
    const float *W2a = 0, *W2b = 0, *b2a = 0, *b2b = 0;
    for (int i = 0; i < n_in; i++) {
        if (i == i_nodes || i == i_edges) continue;
        int s = in_sizes[i];
        const float* p = (const float*)d_in[i];
        if (s == DIM * DIM)        { if (!W1a) W1a = p; else W1b = p; }
        else if (s == DIM)         { if (!b1a) b1a = p; else b1b = p; }
        else if (s == DIM * NCLS)  W2a = p;
        else if (s == NCLS * NCLS) W2b = p;
        else if (s == NCLS)        { if (!b2a) b2a = p; else b2b = p; }
    }
    float* out = (float*)d_out;

    const int g2b_smem = G2B_SMEM_FLOATS * (int)sizeof(float);
    cudaFuncSetAttribute(gemm1_kernel, cudaFuncAttributeMaxDynamicSharedMemorySize, G1_SMEM_BYTES);
    cudaFuncSetAttribute(gemm2b_kernel, cudaFuncAttributeMaxDynamicSharedMemorySize, g2b_smem);

    void* deg_ptr;
    cudaGetSymbolAddress(&deg_ptr, g_deg);

    int nb = (n + SCB - 1) / SCB;  // 25 for n=100k (<=64 required)

    // weight pre-conversion (once) + CSR build
    cudaMemsetAsync(deg_ptr, 0, (size_t)n * sizeof(int));
    convert_weights_kernel<<<32, 256>>>(W1a, W1b, W2a);
    hist_kernel<<<(m + 255) / 256, 256>>>(ei, m);
    scan_partial_kernel<<<nb, 256>>>(n);
    scan_final_kernel<<<nb, 256>>>(n, nb);
    fill_kernel<<<(m + 255) / 256, 256>>>(ei, m);

    // layer 1 + y1 projection (x1 never materialized)
    agg_kernel<<<((size_t)n * 32 + 255) / 256, 256>>>((const float4*)x0, n);
    gemm1_kernel<<<(n + 63) / 64, 256, G1_SMEM_BYTES>>>(b1a, b1b, n);

    // layer 2: fused aggregate + tiny GEMM + softmax
    gemm2b_kernel<<<(n + G2B_ROWS - 1) / G2B_ROWS, 256, g2b_smem>>>(b2a, W2b, b2b, out, n);
}

// round 16
// speedup vs baseline: 2.4779x; 1.0254x over previous
#include <cuda_runtime.h>
#include <cuda_bf16.h>
#include <math.h>

#define N_NODES_MAX 100000
#define N_EDGES_MAX 1600000
#define DIM 128
#define NCLS 40
#define SCB 1024  // elements per scan block (4 per thread)

// ---------------- bf16 split helpers ----------------------------------------
__device__ __forceinline__ unsigned pack_bf2(__nv_bfloat16 a, __nv_bfloat16 b) {
    __nv_bfloat162 t;
    t.x = a; t.y = b;
    return *reinterpret_cast<unsigned*>(&t);
}
__device__ __forceinline__ void split_bf(float f, __nv_bfloat16& hi, __nv_bfloat16& lo) {
    hi = __float2bfloat16_rn(f);
    lo = __float2bfloat16_rn(f - __bfloat162float(hi));
}
__device__ __forceinline__ void mma_bf16(float* c, unsigned a0, unsigned a1,
                                         unsigned a2, unsigned a3,
                                         unsigned b0, unsigned b1) {
    asm volatile(
        "mma.sync.aligned.m16n8k16.row.col.f32.bf16.bf16.f32 "
        "{%0,%1,%2,%3}, {%4,%5,%6,%7}, {%8,%9}, {%0,%1,%2,%3};"
        : "+f"(c[0]), "+f"(c[1]), "+f"(c[2]), "+f"(c[3])
        : "r"(a0), "r"(a1), "r"(a2), "r"(a3), "r"(b0), "r"(b1));
}

// ---------------- scratch (static device allocations; no cudaMalloc) -------
__device__ int g_deg[N_NODES_MAX];
__device__ int g_offs[N_NODES_MAX + 1];
__device__ int g_cur[N_NODES_MAX];
__device__ int g_csr[N_EDGES_MAX];
__device__ int g_bsum[128];
__device__ __align__(16) float g_agg[(size_t)N_NODES_MAX * DIM];
__device__ __align__(16) float g_y1[(size_t)N_NODES_MAX * NCLS];
// pre-converted weights: packed bf16 (hi,lo) pairs in n-major [n][kpair] layout
__device__ unsigned g_wth1a[128 * 64];
__device__ unsigned g_wtl1a[128 * 64];
__device__ unsigned g_wth1b[128 * 64];
__device__ unsigned g_wtl1b[128 * 64];
__device__ unsigned g_wth2a[40 * 64];
__device__ unsigned g_wtl2a[40 * 64];

// ---------------- weight pre-conversion (runs once) -------------------------
__global__ void convert_weights_kernel(const float* __restrict__ W1a,
                                       const float* __restrict__ W1b,
                                       const float* __restrict__ W2a) {
    int i = blockIdx.x * blockDim.x + threadIdx.x;
    if (i < 8192) {
        int kp = i >> 7, nn = i & 127;
        __nv_bfloat16 h0, l0, h1, l1;
        float f0 = W1a[(2 * kp) * 128 + nn];
        float f1 = W1a[(2 * kp + 1) * 128 + nn];
        split_bf(f0, h0, l0); split_bf(f1, h1, l1);
        g_wth1a[nn * 64 + kp] = pack_bf2(h0, h1);
        g_wtl1a[nn * 64 + kp] = pack_bf2(l0, l1);
        f0 = W1b[(2 * kp) * 128 + nn];
        f1 = W1b[(2 * kp + 1) * 128 + nn];
        split_bf(f0, h0, l0); split_bf(f1, h1, l1);
        g_wth1b[nn * 64 + kp] = pack_bf2(h0, h1);
        g_wtl1b[nn * 64 + kp] = pack_bf2(l0, l1);
    }
    if (i < 2560) {
        int kp = i / 40, nn = i - kp * 40;
        __nv_bfloat16 h0, l0, h1, l1;
        float f0 = W2a[(2 * kp) * 40 + nn];
        float f1 = W2a[(2 * kp + 1) * 40 + nn];
        split_bf(f0, h0, l0); split_bf(f1, h1, l1);
        g_wth2a[nn * 64 + kp] = pack_bf2(h0, h1);
        g_wtl2a[nn * 64 + kp] = pack_bf2(l0, l1);
    }
}

// ---------------- CSR build -------------------------------------------------
// hist: 4 independent int4 loads per thread (8 edges) -> MLP=4 on the DRAM stream
__global__ __launch_bounds__(256) void hist_kernel(const int4* __restrict__ e4, int m4,
                                                   const int2* __restrict__ e, int m) {
    int i = blockIdx.x * blockDim.x + threadIdx.x;
    int gs = gridDim.x * blockDim.x;
    int j0 = i, j1 = i + gs, j2 = i + 2 * gs, j3 = i + 3 * gs;
    int4 p0, p1, p2, p3;
    bool v0 = j0 < m4, v1 = j1 < m4, v2 = j2 < m4, v3 = j3 < m4;
    if (v0) p0 = e4[j0];
    if (v1) p1 = e4[j1];
    if (v2) p2 = e4[j2];
    if (v3) p3 = e4[j3];
    if (v0) { atomicAdd(&g_deg[p0.y], 1); atomicAdd(&g_deg[p0.w], 1); }
    if (v1) { atomicAdd(&g_deg[p1.y], 1); atomicAdd(&g_deg[p1.w], 1); }
    if (v2) { atomicAdd(&g_deg[p2.y], 1); atomicAdd(&g_deg[p2.w], 1); }
    if (v3) { atomicAdd(&g_deg[p3.y], 1); atomicAdd(&g_deg[p3.w], 1); }
    if (i == 0 && (m & 1)) atomicAdd(&g_deg[e[m - 1].y], 1);
}

__global__ __launch_bounds__(256) void scan_partial_kernel(int n) {
    __shared__ int s[SCB];
    __shared__ int ws[8];
    int base = blockIdx.x * SCB;
    int tid = threadIdx.x;
    for (int j = tid; j < SCB; j += 256)
        s[j] = (base + j < n) ? g_deg[base + j] : 0;
    __syncthreads();
    int mysum = 0;
#pragma unroll
    for (int j = 0; j < 4; j++) mysum += s[tid * 4 + j];
    int lane = tid & 31, wid = tid >> 5;
    int v = mysum;
#pragma unroll
    for (int o = 16; o > 0; o >>= 1) v += __shfl_down_sync(0xffffffffu, v, o);
    if (lane == 0) ws[wid] = v;
    __syncthreads();
    if (tid == 0) {
        int t = 0;
#pragma unroll
        for (int i = 0; i < 8; i++) t += ws[i];
        g_bsum[blockIdx.x] = t;
    }
}

// per-block scan; block sums prefixed inline
__global__ __launch_bounds__(256) void scan_final_kernel(int n, int nb) {
    __shared__ int s[SCB];
    __shared__ int ws[8];
    __shared__ int boff_s;
    int base = blockIdx.x * SCB;
    int tid = threadIdx.x;
    if (tid == 0) {
        int acc = 0;
        for (int b = 0; b < nb; b++) {
            if (b == blockIdx.x) boff_s = acc;
            acc += g_bsum[b];
        }
        if (blockIdx.x == nb - 1) g_offs[n] = acc;
    }
    for (int j = tid; j < SCB; j += 256)
        s[j] = (base + j < n) ? g_deg[base + j] : 0;
    __syncthreads();
    int mysum = 0;
#pragma unroll
    for (int j = 0; j < 4; j++) mysum += s[tid * 4 + j];
    int lane = tid & 31, wid = tid >> 5;
    int v = mysum;
#pragma unroll
    for (int o = 1; o < 32; o <<= 1) {
        int u = __shfl_up_sync(0xffffffffu, v, o);
        if (lane >= o) v += u;
    }
    if (lane == 31) ws[wid] = v;
    __syncthreads();
    if (wid == 0 && lane < 8) {
        int w = ws[lane];
#pragma unroll
        for (int o = 1; o < 8; o <<= 1) {
            int u = __shfl_up_sync(0xffu, w, o);
            if (lane >= o) w += u;
        }
        ws[lane] = w;
    }
    __syncthreads();
    int run = (v - mysum) + ((wid > 0) ? ws[wid - 1] : 0) + boff_s;
#pragma unroll
    for (int j = 0; j < 4; j++) {
        int idx = tid * 4 + j;
        int t = s[idx];
        s[idx] = run;
        run += t;
    }
    __syncthreads();
    for (int j = tid; j < SCB; j += 256) {
        int gi = base + j;
        if (gi < n) { g_offs[gi] = s[j]; g_cur[gi] = s[j]; }
    }
}

// fill: 4 independent (load -> 2 atomic -> 2 store) chains per thread
__global__ __launch_bounds__(256) void fill_kernel(const int4* __restrict__ e4, int m4,
                                                   const int2* __restrict__ e, int m) {
    int i = blockIdx.x * blockDim.x + threadIdx.x;
    int gs = gridDim.x * blockDim.x;
    int j0 = i, j1 = i + gs, j2 = i + 2 * gs, j3 = i + 3 * gs;
    int4 p0, p1, p2, p3;
    bool v0 = j0 < m4, v1 = j1 < m4, v2 = j2 < m4, v3 = j3 < m4;
    if (v0) p0 = e4[j0];
    if (v1) p1 = e4[j1];
    if (v2) p2 = e4[j2];
    if (v3) p3 = e4[j3];
    int q0a = 0, q0b = 0, q1a = 0, q1b = 0, q2a = 0, q2b = 0, q3a = 0, q3b = 0;
    if (v0) { q0a = atomicAdd(&g_cur[p0.y], 1); q0b = atomicAdd(&g_cur[p0.w], 1); }
    if (v1) { q1a = atomicAdd(&g_cur[p1.y], 1); q1b = atomicAdd(&g_cur[p1.w], 1); }
    if (v2) { q2a = atomicAdd(&g_cur[p2.y], 1); q2b = atomicAdd(&g_cur[p2.w], 1); }
    if (v3) { q3a = atomicAdd(&g_cur[p3.y], 1); q3b = atomicAdd(&g_cur[p3.w], 1); }
    if (v0) { g_csr[q0a] = p0.x; g_csr[q0b] = p0.z; }
    if (v1) { g_csr[q1a] = p1.x; g_csr[q1b] = p1.z; }
    if (v2) { g_csr[q2a] = p2.x; g_csr[q2b] = p2.z; }
    if (v3) { g_csr[q3a] = p3.x; g_csr[q3b] = p3.z; }
    if (i == 0 && (m & 1)) {
        int2 ed = e[m - 1];
        int p = atomicAdd(&g_cur[ed.y], 1);
        g_csr[p] = ed.x;
    }
}

// ---------------- agg1: warp per node, 128-dim gather -----------------------
__global__ __launch_bounds__(256) void agg_kernel(const float4* __restrict__ x4, int n) {
    int gt = blockIdx.x * blockDim.x + threadIdx.x;
    int w = gt >> 5;
    int lane = gt & 31;
    if (w >= n) return;
    float4* o4 = (float4*)g_agg;
    float4 acc = x4[(size_t)w * 32 + lane];
    int s0 = g_offs[w], s1 = g_offs[w + 1];
    for (int j = s0; j < s1; j++) {
        int s = g_csr[j];
        float4 v = __ldg(&x4[(size_t)s * 32 + lane]);
        acc.x += v.x; acc.y += v.y; acc.z += v.z; acc.w += v.w;
    }
    o4[(size_t)w * 32 + lane] = acc;
}

// ---------------- layer 1 + y1 projection via split-bf16 MMA ----------------
#define SAW 68
#define OFF_A2H 0
#define OFF_A2L (OFF_A2H + 64 * SAW)
#define OFF_WTH (OFF_A2L + 64 * SAW)
#define OFF_WTL (OFF_WTH + 128 * SAW)
#define OFF_BSA (OFF_WTL + 128 * SAW)
#define OFF_BSB (OFF_BSA + 128)
#define G1_SMEM_WORDS (OFF_BSB + 128)
#define G1_SMEM_BYTES (G1_SMEM_WORDS * 4)

__device__ __forceinline__ void g1_load_W128(unsigned* WTH, unsigned* WTL,
                                             const unsigned* __restrict__ GH,
                                             const unsigned* __restrict__ GL, int tid) {
    for (int i = tid; i < 8192; i += 256) {
        int kp = i & 63, nn = i >> 6;
        WTH[nn * SAW + kp] = GH[i];
        WTL[nn * SAW + kp] = GL[i];
    }
}

__global__ __launch_bounds__(256) void gemm1_kernel(
    const float* __restrict__ b1a, const float* __restrict__ b1b, int n) {
    extern __shared__ unsigned su[];
    unsigned* A2H = su + OFF_A2H;
    unsigned* A2L = su + OFF_A2L;
    unsigned* WTH = su + OFF_WTH;
    unsigned* WTL = su + OFF_WTL;
    float* bsA = (float*)(su + OFF_BSA);
    float* bsB = (float*)(su + OFF_BSB);

    int tid = threadIdx.x;
    int lane = tid & 31, wid = tid >> 5;
    int r0 = (wid >> 1) << 4;   // warp row base (0,16,32,48)
    int n0 = (wid & 1) << 6;    // warp col base (0,64)
    int row0 = blockIdx.x * 64;

    // stage A tile (convert f32 -> bf16 hi/lo pairs)
    for (int i = tid; i < 64 * 32; i += 256) {
        int r = i >> 5, c = i & 31;
        float4 v = (row0 + r < n) ? ((const float4*)g_agg)[(size_t)(row0 + r) * 32 + c]
                                  : make_float4(0.f, 0.f, 0.f, 0.f);
        __nv_bfloat16 hx, lx, hy, ly, hz, lz, hw, lw;
        split_bf(v.x, hx, lx); split_bf(v.y, hy, ly);
        split_bf(v.z, hz, lz); split_bf(v.w, hw, lw);
        A2H[r * SAW + 2 * c + 0] = pack_bf2(hx, hy);
        A2H[r * SAW + 2 * c + 1] = pack_bf2(hz, hw);
        A2L[r * SAW + 2 * c + 0] = pack_bf2(lx, ly);
        A2L[r * SAW + 2 * c + 1] = pack_bf2(lz, lw);
    }
    g1_load_W128(WTH, WTL, g_wth1a, g_wtl1a, tid);
    if (tid < 128) { bsA[tid] = b1a[tid]; bsB[tid] = b1b[tid]; }
    __syncthreads();

    float acc[8][4];
#pragma unroll
    for (int t = 0; t < 8; t++)
#pragma unroll
        for (int q = 0; q < 4; q++) acc[t][q] = 0.f;

    int arow = (r0 + (lane >> 2)) * SAW + (lane & 3);
    // ---------------- phase 1 mma ----------------
    for (int kk = 0; kk < 8; kk++) {
        int aw = arow + kk * 8;
        unsigned ah0 = A2H[aw], ah1 = A2H[aw + 8 * SAW];
        unsigned ah2 = A2H[aw + 4], ah3 = A2H[aw + 8 * SAW + 4];
        unsigned al0 = A2L[aw], al1 = A2L[aw + 8 * SAW];
        unsigned al2 = A2L[aw + 4], al3 = A2L[aw + 8 * SAW + 4];
#pragma unroll
        for (int t = 0; t < 8; t++) {
            int bw = (n0 + t * 8 + (lane >> 2)) * SAW + kk * 8 + (lane & 3);
            unsigned bh0 = WTH[bw], bh1 = WTH[bw + 4];
            unsigned bl0 = WTL[bw], bl1 = WTL[bw + 4];
            mma_bf16(acc[t], ah0, ah1, ah2, ah3, bh0, bh1);
            mma_bf16(acc[t], ah0, ah1, ah2, ah3, bl0, bl1);
            mma_bf16(acc[t], al0, al1, al2, al3, bh0, bh1);
        }
    }
    __syncthreads();

    // epilogue 1: T = relu(acc + b1a) -> A2; load W1b
    {
        int row = r0 + (lane >> 2);
#pragma unroll
        for (int t = 0; t < 8; t++) {
            int col = n0 + t * 8 + (lane & 3) * 2;
            int pair = col >> 1;
            float h00 = fmaxf(acc[t][0] + bsA[col], 0.f);
            float h01 = fmaxf(acc[t][1] + bsA[col + 1], 0.f);
            float h10 = fmaxf(acc[t][2] + bsA[col], 0.f);
            float h11 = fmaxf(acc[t][3] + bsA[col + 1], 0.f);
            __nv_bfloat16 h, l, h2, l2;
            split_bf(h00, h, l); split_bf(h01, h2, l2);
            A2H[row * SAW + pair] = pack_bf2(h, h2);
            A2L[row * SAW + pair] = pack_bf2(l, l2);
            split_bf(h10, h, l); split_bf(h11, h2, l2);
            A2H[(row + 8) * SAW + pair] = pack_bf2(h, h2);
            A2L[(row + 8) * SAW + pair] = pack_bf2(l, l2);
            acc[t][0] = acc[t][1] = acc[t][2] = acc[t][3] = 0.f;
        }
    }
    g1_load_W128(WTH, WTL, g_wth1b, g_wtl1b, tid);
    __syncthreads();

    // ---------------- phase 2 mma ----------------
    for (int kk = 0; kk < 8; kk++) {
        int aw = arow + kk * 8;
        unsigned ah0 = A2H[aw], ah1 = A2H[aw + 8 * SAW];
        unsigned ah2 = A2H[aw + 4], ah3 = A2H[aw + 8 * SAW + 4];
        unsigned al0 = A2L[aw], al1 = A2L[aw + 8 * SAW];
        unsigned al2 = A2L[aw + 4], al3 = A2L[aw + 8 * SAW + 4];
#pragma unroll
        for (int t = 0; t < 8; t++) {
            int bw = (n0 + t * 8 + (lane >> 2)) * SAW + kk * 8 + (lane & 3);
            unsigned bh0 = WTH[bw], bh1 = WTH[bw + 4];
            unsigned bl0 = WTL[bw], bl1 = WTL[bw + 4];
            mma_bf16(acc[t], ah0, ah1, ah2, ah3, bh0, bh1);
            mma_bf16(acc[t], ah0, ah1, ah2, ah3, bl0, bl1);
            mma_bf16(acc[t], al0, al1, al2, al3, bh0, bh1);
        }
    }
    __syncthreads();  // phase-2 reads complete before overwrite

    // epilogue 2: X = relu(acc + b1b) -> A2 (hi/lo); load W2a
    {
        int row = r0 + (lane >> 2);
#pragma unroll
        for (int t = 0; t < 8; t++) {
            int col = n0 + t * 8 + (lane & 3) * 2;
            int pair = col >> 1;
            float h00 = fmaxf(acc[t][0] + bsB[col], 0.f);
            float h01 = fmaxf(acc[t][1] + bsB[col + 1], 0.f);
            float h10 = fmaxf(acc[t][2] + bsB[col], 0.f);
            float h11 = fmaxf(acc[t][3] + bsB[col + 1], 0.f);
            __nv_bfloat16 h, l, h2, l2;
            split_bf(h00, h, l); split_bf(h01, h2, l2);
            A2H[row * SAW + pair] = pack_bf2(h, h2);
            A2L[row * SAW + pair] = pack_bf2(l, l2);
            split_bf(h10, h, l); split_bf(h11, h2, l2);
            A2H[(row + 8) * SAW + pair] = pack_bf2(h, h2);
            A2L[(row + 8) * SAW + pair] = pack_bf2(l, l2);
        }
    }
    for (int i = tid; i < 2560; i += 256) {
        int kp = i & 63, nn = i >> 6;
        WTH[nn * SAW + kp] = g_wth2a[i];
        WTL[nn * SAW + kp] = g_wtl2a[i];
    }
    __syncthreads();

    // ---------------- phase 3 mma: y1 = X @ W2a (warps with wid&1==0) -------
    if ((wid & 1) == 0) {
        float accy[5][4];
#pragma unroll
        for (int t = 0; t < 5; t++)
#pragma unroll
            for (int q = 0; q < 4; q++) accy[t][q] = 0.f;

        for (int kk = 0; kk < 8; kk++) {
            int aw = arow + kk * 8;
            unsigned ah0 = A2H[aw], ah1 = A2H[aw + 8 * SAW];
            unsigned ah2 = A2H[aw + 4], ah3 = A2H[aw + 8 * SAW + 4];
            unsigned al0 = A2L[aw], al1 = A2L[aw + 8 * SAW];
            unsigned al2 = A2L[aw + 4], al3 = A2L[aw + 8 * SAW + 4];
#pragma unroll
            for (int t = 0; t < 5; t++) {
                int bw = (t * 8 + (lane >> 2)) * SAW + kk * 8 + (lane & 3);
                unsigned bh0 = WTH[bw], bh1 = WTH[bw + 4];
                unsigned bl0 = WTL[bw], bl1 = WTL[bw + 4];
                mma_bf16(accy[t], ah0, ah1, ah2, ah3, bh0, bh1);
                mma_bf16(accy[t], ah0, ah1, ah2, ah3, bl0, bl1);
                mma_bf16(accy[t], al0, al1, al2, al3, bh0, bh1);
            }
        }
        int row = row0 + r0 + (lane >> 2);
#pragma unroll
        for (int t = 0; t < 5; t++) {
            int col = t * 8 + (lane & 3) * 2;
            if (row < n) {
                float2 o; o.x = accy[t][0]; o.y = accy[t][1];
                *(float2*)&g_y1[(size_t)row * 40 + col] = o;
            }
            if (row + 8 < n) {
                float2 o; o.x = accy[t][2]; o.y = accy[t][3];
                *(float2*)&g_y1[(size_t)(row + 8) * 40 + col] = o;
            }
        }
    }
}

// ---------------- final: out = softmax(relu(agg(y1) + b2a) @ W2b + b2b) -----
#define G2B_ROWS 256
#define G2B_SMEM_FLOATS (G2B_ROWS * 41 + 40 * 40 + 40 + 40)
__global__ __launch_bounds__(256) void gemm2b_kernel(
    const float* __restrict__ b2a, const float* __restrict__ W2b,
    const float* __restrict__ b2b, float* __restrict__ out, int n) {
    extern __shared__ float sm[];
    float* As = sm;
    float* Wb = sm + G2B_ROWS * 41;
    float* ba = Wb + 40 * 40;
    float* bb = ba + 40;

    int tid = threadIdx.x;
    int lane = tid & 31, wid = tid >> 5;
    int row0 = blockIdx.x * G2B_ROWS;
    const float2* y2 = (const float2*)g_y1;

    for (int i = 0; i < 32; i++) {
        int r = wid * 32 + i;
        int row = row0 + r;
        float2 acc = make_float2(0.f, 0.f);
        if (row < n) {
            int s0 = g_offs[row], s1 = g_offs[row + 1];
            if (lane < 20) {
                acc = y2[(size_t)row * 20 + lane];
                for (int j = s0; j < s1; j++) {
                    int s = g_csr[j];
                    float2 v = __ldg(&y2[(size_t)s * 20 + lane]);
                    acc.x += v.x; acc.y += v.y;
                }
            }
        }
        if (lane < 20) {
            As[r * 41 + 2 * lane + 0] = acc.x;
            As[r * 41 + 2 * lane + 1] = acc.y;
        }
    }
    for (int i = tid; i < 1600; i += 256) Wb[i] = W2b[i];
    if (tid < 40) { ba[tid] = b2a[tid]; bb[tid] = b2b[tid]; }
    __syncthreads();

    float h[40];
    const float* arow = &As[tid * 41];
#pragma unroll
    for (int c = 0; c < 40; c++) h[c] = fmaxf(arow[c] + ba[c], 0.f);

    float o[40];
#pragma unroll
    for (int c = 0; c < 40; c++) o[c] = bb[c];
#pragma unroll 4
    for (int k = 0; k < 40; k++) {
        float a = h[k];
        const float4* w = (const float4*)&Wb[k * 40];
#pragma unroll
        for (int q = 0; q < 10; q++) {
            float4 wv = w[q];
            o[q * 4 + 0] = fmaf(a, wv.x, o[q * 4 + 0]);
            o[q * 4 + 1] = fmaf(a, wv.y, o[q * 4 + 1]);
            o[q * 4 + 2] = fmaf(a, wv.z, o[q * 4 + 2]);
            o[q * 4 + 3] = fmaf(a, wv.w, o[q * 4 + 3]);
        }
    }
    float mx = o[0];
#pragma unroll
    for (int c = 1; c < 40; c++) mx = fmaxf(mx, o[c]);
    float s = 0.f;
#pragma unroll
    for (int c = 0; c < 40; c++) { float e = __expf(o[c] - mx); o[c] = e; s += e; }
    float inv = 1.0f / s;
#pragma unroll
    for (int c = 0; c < 40; c++) As[tid * 41 + c] = o[c] * inv;
    __syncthreads();
    for (int i = tid; i < G2B_ROWS * 40; i += 256) {
        int r = i / 40, c = i - r * 40;
        int row = row0 + r;
        if (row < n) out[(size_t)row * 40 + c] = As[r * 41 + c];
    }
}

// ---------------- launcher --------------------------------------------------
extern "C" void kernel_launch(void* const* d_in, const int* in_sizes, int n_in,
                              void* d_out, int out_size) {
    int i_nodes = 0, i_edges = -1;
    for (int i = 1; i < n_in; i++)
        if (in_sizes[i] > in_sizes[i_nodes]) i_nodes = i;
    for (int i = 0; i < n_in; i++) {
        if (i == i_nodes) continue;
        if (i_edges < 0 || in_sizes[i] > in_sizes[i_edges]) i_edges = i;
    }

    const float* x0  = (const float*)d_in[i_nodes];
    const int2*  ei  = (const int2*)d_in[i_edges];
    int n = in_sizes[i_nodes] / DIM;
    int m = in_sizes[i_edges] / 2;
    int m4 = m >> 1;  // int4 = 2 edges

    const float *W1a = 0, *W1b = 0, *b1a = 0, *b1b = 0;
    const float *W2a = 0, *W2b = 0, *b2a = 0, *b2b = 0;
    for (int i = 0; i < n_in; i++) {
        if (i == i_nodes || i == i_edges) continue;
        int s = in_sizes[i];
        const float* p = (const float*)d_in[i];
        if (s == DIM * DIM)        { if (!W1a) W1a = p; else W1b = p; }
        else if (s == DIM)         { if (!b1a) b1a = p; else b1b = p; }
        else if (s == DIM * NCLS)  W2a = p;
        else if (s == NCLS * NCLS) W2b = p;
        else if (s == NCLS)        { if (!b2a) b2a = p; else b2b = p; }
    }
    float* out = (float*)d_out;

    const int g2b_smem = G2B_SMEM_FLOATS * (int)sizeof(float);
    cudaFuncSetAttribute(gemm1_kernel, cudaFuncAttributeMaxDynamicSharedMemorySize, G1_SMEM_BYTES);
    cudaFuncSetAttribute(gemm2b_kernel, cudaFuncAttributeMaxDynamicSharedMemorySize, g2b_smem);

    void* deg_ptr;
    cudaGetSymbolAddress(&deg_ptr, g_deg);

    int nb = (n + SCB - 1) / SCB;             // 98 for n=100k (<=128 required)
    int eb = (m4 + 1023) / 1024;              // 4 int4 per thread, 256 threads

    // weight pre-conversion (once) + CSR build
    cudaMemsetAsync(deg_ptr, 0, (size_t)n * sizeof(int));
    convert_weights_kernel<<<32, 256>>>(W1a, W1b, W2a);
    hist_kernel<<<eb, 256>>>((const int4*)ei, m4, ei, m);
    scan_partial_kernel<<<nb, 256>>>(n);
    scan_final_kernel<<<nb, 256>>>(n, nb);
    fill_kernel<<<eb, 256>>>((const int4*)ei, m4, ei, m);

    // layer 1 + y1 projection (x1 never materialized)
    agg_kernel<<<((size_t)n * 32 + 255) / 256, 256>>>((const float4*)x0, n);
    gemm1_kernel<<<(n + 63) / 64, 256, G1_SMEM_BYTES>>>(b1a, b1b, n);

    // layer 2: fused aggregate + tiny GEMM + softmax
    gemm2b_kernel<<<(n + G2B_ROWS - 1) / G2B_ROWS, 256, g2b_smem>>>(b2a, W2b, b2b, out, n);
}